// round 1
// baseline (speedup 1.0000x reference)
#include <cuda_runtime.h>
#include <cuda_bf16.h>
#include <math.h>

// ---------------------------------------------------------------------------
// Problem constants
// ---------------------------------------------------------------------------
#define BATCH   16
#define CIN     3
#define IMG     256
#define PSZ     16
#define HPAT    16          // IMG/PSZ
#define NPATCH  256         // HPAT*HPAT
#define C5      15          // 5*CIN
#define PD      3840        // PSZ*PSZ*C5
#define DMODEL  768
#define DEPTH   8
#define MLP     3072
#define NCLS    1000
#define TTOK    257         // NPATCH + 1
#define NT      (BATCH*TTOK)        // 4112
#define NROWS_EMBED (BATCH*NPATCH)  // 4096
#define NHEAD   384         // DMODEL/2
#define ER      2

// ---------------------------------------------------------------------------
// Scratch (device globals; no allocation allowed)
// ---------------------------------------------------------------------------
__device__ float g_patches[NROWS_EMBED * PD];   // 4096 x 3840
__device__ float g_x[NT * DMODEL];              // 4112 x 768
__device__ float g_xn[NT * DMODEL];
__device__ float g_feat[NT * 3 * DMODEL];       // 4112 x 2304
__device__ float g_o[NT * DMODEL];
__device__ float g_hmid[NT * MLP];              // 4112 x 3072
__device__ float g_lb[DEPTH * DMODEL];
__device__ float g_cls[BATCH * DMODEL];

// ---------------------------------------------------------------------------
// Helpers
// ---------------------------------------------------------------------------
__device__ __forceinline__ float gelu_exact(float x) {
    return 0.5f * x * (1.f + erff(x * 0.70710678118654752440f));
}

__device__ __forceinline__ float blockReduceSum(float v) {
    __shared__ float sh[32];
    __shared__ float res;
    int lane = threadIdx.x & 31;
    int wid  = threadIdx.x >> 5;
    #pragma unroll
    for (int o = 16; o > 0; o >>= 1) v += __shfl_down_sync(0xffffffffu, v, o);
    if (lane == 0) sh[wid] = v;
    __syncthreads();
    int nw = (blockDim.x + 31) >> 5;
    v = (threadIdx.x < nw) ? sh[threadIdx.x] : 0.f;
    if (wid == 0) {
        #pragma unroll
        for (int o = 16; o > 0; o >>= 1) v += __shfl_down_sync(0xffffffffu, v, o);
        if (lane == 0) res = v;
    }
    __syncthreads();
    return res;
}

// ---------------------------------------------------------------------------
// 1) Shifted-patch extraction + LayerNorm over PD features
//    grid = 4096 blocks (b*256 + patch), 256 threads
// ---------------------------------------------------------------------------
__global__ __launch_bounds__(256)
void patchln_k(const float* __restrict__ img,
               const float* __restrict__ ln_g,
               const float* __restrict__ ln_b,
               float* __restrict__ out)
{
    const int blk = blockIdx.x;
    const int b   = blk >> 8;
    const int pt  = blk & 255;
    const int ph  = pt >> 4;
    const int pw  = pt & 15;

    __shared__ float vals[PD];

    const int sh_tab[5] = {0, 0, 0, 1, -1};
    const int sw_tab[5] = {0, 1, -1, 0, 0};

    float s = 0.f, ss = 0.f;
    for (int f = threadIdx.x; f < PD; f += 256) {
        int py  = f / (PSZ * C5);
        int rem = f - py * (PSZ * C5);
        int px  = rem / C5;
        int c   = rem - px * C5;
        int g   = c / CIN;
        int ch  = c - g * CIN;
        int row = ph * PSZ + py - sh_tab[g];
        int col = pw * PSZ + px - sw_tab[g];
        float v = 0.f;
        if (row >= 0 && row < IMG && col >= 0 && col < IMG)
            v = img[(((long)b * CIN + ch) * IMG + row) * IMG + col];
        vals[f] = v;
        s  += v;
        ss += v * v;
    }
    float tsum  = blockReduceSum(s);
    float tsum2 = blockReduceSum(ss);
    float mean  = tsum * (1.f / PD);
    float var   = tsum2 * (1.f / PD) - mean * mean;
    float rstd  = rsqrtf(var + 1e-5f);
    __syncthreads();
    float* orow = out + (long)blk * PD;
    for (int f = threadIdx.x; f < PD; f += 256)
        orow[f] = (vals[f] - mean) * rstd * ln_g[f] + ln_b[f];
}

// ---------------------------------------------------------------------------
// 2) lower-bounds: softmax over depth axis, cumsum, minus first
// ---------------------------------------------------------------------------
__global__ void lb_k(const float* __restrict__ lbin, float* __restrict__ lbout)
{
    int d = blockIdx.x * blockDim.x + threadIdx.x;
    if (d >= DMODEL) return;
    float v[DEPTH];
    float m = -1e30f;
    #pragma unroll
    for (int i = 0; i < DEPTH; i++) { v[i] = lbin[i * DMODEL + d]; m = fmaxf(m, v[i]); }
    float s = 0.f;
    #pragma unroll
    for (int i = 0; i < DEPTH; i++) { v[i] = expf(v[i] - m); s += v[i]; }
    float inv = 1.f / s;
    float c = 0.f;
    float c0 = v[0] * inv;
    #pragma unroll
    for (int i = 0; i < DEPTH; i++) { c += v[i] * inv; lbout[i * DMODEL + d] = c - c0; }
}

// ---------------------------------------------------------------------------
// 3) cls row init: x[b,0,:] = cls_token + pos_emb[0]
// ---------------------------------------------------------------------------
__global__ void cls_k(const float* __restrict__ cls_token,
                      const float* __restrict__ pos,
                      float* __restrict__ x)
{
    int i = blockIdx.x * blockDim.x + threadIdx.x;
    if (i >= BATCH * DMODEL) return;
    int b = i / DMODEL, d = i - b * DMODEL;
    x[(long)b * TTOK * DMODEL + d] = cls_token[d] + pos[d];
}

// ---------------------------------------------------------------------------
// 4) SGEMM 128x128x8, 8x8 per thread, fused epilogues
// ---------------------------------------------------------------------------
#define EPI_STORE      0
#define EPI_EMBED      1   // + bias + pos_emb, scatter rows past cls slots
#define EPI_RESID      2   // C += acc
#define EPI_BIAS_GELU  3   // C = gelu(acc + bias)
#define EPI_BIAS_RESID 4   // C += acc + bias

template<int EPI>
__global__ __launch_bounds__(256)
void sgemm_k(const float* __restrict__ A, const float* __restrict__ B,
             float* __restrict__ C, const float* __restrict__ bias,
             const float* __restrict__ extra, int M, int N, int K)
{
    __shared__ float As[8][128];
    __shared__ float Bs[8][132];

    const int tid = threadIdx.x;
    const int tx = tid & 15;
    const int ty = tid >> 4;
    const int rowBase = blockIdx.y * 128;
    const int colBase = blockIdx.x * 128;

    float acc[8][8];
    #pragma unroll
    for (int i = 0; i < 8; i++)
        #pragma unroll
        for (int j = 0; j < 8; j++) acc[i][j] = 0.f;

    for (int k0 = 0; k0 < K; k0 += 8) {
        #pragma unroll
        for (int l = 0; l < 4; l++) {
            int idx = tid + l * 256;
            int m  = idx >> 3;
            int kk = idx & 7;
            int gr = rowBase + m;
            As[kk][m] = (gr < M) ? A[(long)gr * K + k0 + kk] : 0.f;
        }
        #pragma unroll
        for (int l = 0; l < 4; l++) {
            int idx = tid + l * 256;
            int kk = idx >> 7;
            int n  = idx & 127;
            int gc = colBase + n;
            Bs[kk][n] = (gc < N) ? B[(long)(k0 + kk) * N + gc] : 0.f;
        }
        __syncthreads();
        #pragma unroll
        for (int kk = 0; kk < 8; kk++) {
            float ra[8], rb[8];
            #pragma unroll
            for (int i = 0; i < 8; i++) ra[i] = As[kk][ty * 8 + i];
            #pragma unroll
            for (int j = 0; j < 8; j++) rb[j] = Bs[kk][tx * 8 + j];
            #pragma unroll
            for (int i = 0; i < 8; i++)
                #pragma unroll
                for (int j = 0; j < 8; j++)
                    acc[i][j] = fmaf(ra[i], rb[j], acc[i][j]);
        }
        __syncthreads();
    }

    #pragma unroll
    for (int i = 0; i < 8; i++) {
        int row = rowBase + ty * 8 + i;
        if (row >= M) continue;
        #pragma unroll
        for (int j = 0; j < 8; j++) {
            int col = colBase + tx * 8 + j;
            if (col >= N) continue;
            float v = acc[i][j];
            if (EPI == EPI_STORE) {
                C[(long)row * N + col] = v;
            } else if (EPI == EPI_EMBED) {
                int b  = row >> 8;          // 256 tokens per image
                int tl = row & 255;
                v += bias[col] + extra[(long)(tl + 1) * N + col];
                C[((long)b * TTOK + 1 + tl) * N + col] = v;
            } else if (EPI == EPI_RESID) {
                long o = (long)row * N + col;
                C[o] += v;
            } else if (EPI == EPI_BIAS_GELU) {
                v += bias[col];
                C[(long)row * N + col] = gelu_exact(v);
            } else if (EPI == EPI_BIAS_RESID) {
                long o = (long)row * N + col;
                C[o] += v + bias[col];
            }
        }
    }
}

// ---------------------------------------------------------------------------
// 5) RMSNorm over D=768, one block per row
// ---------------------------------------------------------------------------
__global__ __launch_bounds__(256)
void rmsnorm_k(const float* __restrict__ x, float* __restrict__ y)
{
    const long row = blockIdx.x;
    const float* xr = x + row * DMODEL;
    float s = 0.f;
    for (int i = threadIdx.x; i < DMODEL; i += 256) { float v = xr[i]; s += v * v; }
    float tot = blockReduceSum(s);
    float r = rsqrtf(tot * (1.f / DMODEL) + 1e-6f);
    float* yr = y + row * DMODEL;
    for (int i = threadIdx.x; i < DMODEL; i += 256) yr[i] = xr[i] * r;
}

// ---------------------------------------------------------------------------
// 6) hGRU2 scan over batch axis. One thread per (token t, head h).
//    State: 2x2 per chain, 16 steps.
// ---------------------------------------------------------------------------
__global__ __launch_bounds__(256)
void hgru_k(const float* __restrict__ feat, const float* __restrict__ lb,
            float* __restrict__ o)
{
    int e = blockIdx.x * blockDim.x + threadIdx.x;
    if (e >= TTOK * NHEAD) return;
    int t = e / NHEAD;
    int h = e - t * NHEAD;

    float lb0 = lb[2 * h];
    float lb1 = lb[2 * h + 1];
    float S00 = 0.f, S01 = 0.f, S10 = 0.f, S11 = 0.f;

    #pragma unroll 1
    for (int n = 0; n < BATCH; n++) {
        const float* r = feat + (long)(n * TTOK + t) * (3 * DMODEL);
        float2 vv = *(const float2*)(r + 2 * h);
        float2 qq = *(const float2*)(r + DMODEL + 2 * h);
        float2 ff = *(const float2*)(r + 2 * DMODEL + 2 * h);
        float v0 = gelu_exact(vv.x), v1 = gelu_exact(vv.y);
        float q0 = gelu_exact(qq.x), q1 = gelu_exact(qq.y);
        float s0 = 1.f / (1.f + expf(-ff.x));
        float s1 = 1.f / (1.f + expf(-ff.y));
        float lam0 = lb0 + (1.f - lb0) * s0;
        float lam1 = lb1 + (1.f - lb1) * s1;
        float k0 = 1.f - lam0, k1 = 1.f - lam1;
        S00 = lam0 * S00 + k0 * v0;  S01 = lam0 * S01 + k0 * v1;
        S10 = lam1 * S10 + k1 * v0;  S11 = lam1 * S11 + k1 * v1;
        float o0 = q0 * S00 + q1 * S10;
        float o1 = q0 * S01 + q1 * S11;
        *(float2*)(o + (long)(n * TTOK + t) * DMODEL + 2 * h) = make_float2(o0, o1);
    }
}

// ---------------------------------------------------------------------------
// 7) final: rmsnorm(x[:,0]) -> layernorm -> g_cls
// ---------------------------------------------------------------------------
__global__ __launch_bounds__(256)
void final_k(const float* __restrict__ x,
             const float* __restrict__ g, const float* __restrict__ bvec,
             float* __restrict__ cls)
{
    int b = blockIdx.x;
    const float* xr = x + (long)b * TTOK * DMODEL;
    __shared__ float y[DMODEL];
    float s = 0.f, ss = 0.f;
    for (int i = threadIdx.x; i < DMODEL; i += 256) {
        float v = xr[i];
        y[i] = v;
        s  += v;
        ss += v * v;
    }
    float tsum  = blockReduceSum(s);
    float tsum2 = blockReduceSum(ss);
    float rstd1 = rsqrtf(tsum2 * (1.f / DMODEL) + 1e-6f);
    float mean  = rstd1 * tsum * (1.f / DMODEL);
    float ez2   = rstd1 * rstd1 * tsum2 * (1.f / DMODEL);
    float var   = ez2 - mean * mean;
    float rstd2 = rsqrtf(var + 1e-5f);
    __syncthreads();
    for (int i = threadIdx.x; i < DMODEL; i += 256) {
        float z = y[i] * rstd1;
        cls[(long)b * DMODEL + i] = (z - mean) * rstd2 * g[i] + bvec[i];
    }
}

// ---------------------------------------------------------------------------
// 8) head: (16x768) @ (768x1000) + bias  -> d_out
// ---------------------------------------------------------------------------
__global__ __launch_bounds__(256)
void head_k(const float* __restrict__ cls, const float* __restrict__ w,
            const float* __restrict__ bias, float* __restrict__ out)
{
    int idx = blockIdx.x * blockDim.x + threadIdx.x;
    if (idx >= BATCH * NCLS) return;
    int b = idx / NCLS, c = idx - b * NCLS;
    const float* xr = cls + (long)b * DMODEL;
    float s = bias[c];
    #pragma unroll 4
    for (int k = 0; k < DMODEL; k++)
        s = fmaf(xr[k], w[(long)k * NCLS + c], s);
    out[idx] = s;
}

// ---------------------------------------------------------------------------
// Launch
// ---------------------------------------------------------------------------
extern "C" void kernel_launch(void* const* d_in, const int* in_sizes, int n_in,
                              void* d_out, int out_size)
{
    const float* img          = (const float*)d_in[0];
    const float* spt_ln_g     = (const float*)d_in[1];
    const float* spt_ln_b     = (const float*)d_in[2];
    const float* spt_w        = (const float*)d_in[3];
    const float* spt_b        = (const float*)d_in[4];
    const float* pos_emb      = (const float*)d_in[5];
    const float* cls_token    = (const float*)d_in[6];
    const float* lower_bounds = (const float*)d_in[7];
    const float* in_proj_w    = (const float*)d_in[8];
    const float* out_proj_w   = (const float*)d_in[9];
    const float* ff_w1        = (const float*)d_in[10];
    const float* ff_b1        = (const float*)d_in[11];
    const float* ff_w2        = (const float*)d_in[12];
    const float* ff_b2        = (const float*)d_in[13];
    const float* head_ln_g    = (const float*)d_in[14];
    const float* head_ln_b    = (const float*)d_in[15];
    const float* head_w       = (const float*)d_in[16];
    const float* head_b       = (const float*)d_in[17];

    float *patches, *x, *xn, *feat, *o, *hmid, *lb, *cls;
    cudaGetSymbolAddress((void**)&patches, g_patches);
    cudaGetSymbolAddress((void**)&x,       g_x);
    cudaGetSymbolAddress((void**)&xn,      g_xn);
    cudaGetSymbolAddress((void**)&feat,    g_feat);
    cudaGetSymbolAddress((void**)&o,       g_o);
    cudaGetSymbolAddress((void**)&hmid,    g_hmid);
    cudaGetSymbolAddress((void**)&lb,      g_lb);
    cudaGetSymbolAddress((void**)&cls,     g_cls);

    // patch extraction + LN
    patchln_k<<<NROWS_EMBED, 256>>>(img, spt_ln_g, spt_ln_b, patches);
    // lower bounds preprocessing
    lb_k<<<(DMODEL + 255) / 256, 256>>>(lower_bounds, lb);
    // cls rows
    cls_k<<<(BATCH * DMODEL + 255) / 256, 256>>>(cls_token, pos_emb, x);
    // patch embed GEMM (scatter + bias + pos_emb)
    {
        dim3 grid((DMODEL + 127) / 128, (NROWS_EMBED + 127) / 128);
        sgemm_k<EPI_EMBED><<<grid, 256>>>(patches, spt_w, x, spt_b, pos_emb,
                                          NROWS_EMBED, DMODEL, PD);
    }

    for (int i = 0; i < DEPTH; i++) {
        rmsnorm_k<<<NT, 256>>>(x, xn);
        {
            dim3 grid((3 * DMODEL + 127) / 128, (NT + 127) / 128);
            sgemm_k<EPI_STORE><<<grid, 256>>>(xn, in_proj_w + (long)i * DMODEL * 3 * DMODEL,
                                              feat, nullptr, nullptr, NT, 3 * DMODEL, DMODEL);
        }
        hgru_k<<<(TTOK * NHEAD + 255) / 256, 256>>>(feat, lb + (long)i * DMODEL, o);
        {
            dim3 grid((DMODEL + 127) / 128, (NT + 127) / 128);
            sgemm_k<EPI_RESID><<<grid, 256>>>(o, out_proj_w + (long)i * DMODEL * DMODEL,
                                              x, nullptr, nullptr, NT, DMODEL, DMODEL);
        }
        rmsnorm_k<<<NT, 256>>>(x, xn);
        {
            dim3 grid((MLP + 127) / 128, (NT + 127) / 128);
            sgemm_k<EPI_BIAS_GELU><<<grid, 256>>>(xn, ff_w1 + (long)i * DMODEL * MLP,
                                                  hmid, ff_b1 + (long)i * MLP, nullptr,
                                                  NT, MLP, DMODEL);
        }
        {
            dim3 grid((DMODEL + 127) / 128, (NT + 127) / 128);
            sgemm_k<EPI_BIAS_RESID><<<grid, 256>>>(hmid, ff_w2 + (long)i * MLP * DMODEL,
                                                   x, ff_b2 + (long)i * DMODEL, nullptr,
                                                   NT, DMODEL, MLP);
        }
    }

    final_k<<<BATCH, 256>>>(x, head_ln_g, head_ln_b, cls);
    head_k<<<(BATCH * NCLS + 255) / 256, 256>>>(cls, head_w, head_b, (float*)d_out);
}

// round 3
// speedup vs baseline: 2.0870x; 2.0870x over previous
#include <cuda_runtime.h>
#include <cuda_bf16.h>
#include <math.h>
#include <stdint.h>

// ---------------------------------------------------------------------------
// Problem constants
// ---------------------------------------------------------------------------
#define BATCH   16
#define CIN     3
#define IMG     256
#define PSZ     16
#define NPATCH  256
#define C5      15
#define PD      3840
#define DMODEL  768
#define DEPTH   8
#define MLP     3072
#define NCLS    1000
#define TTOK    257
#define NT      (BATCH*TTOK)        // 4112
#define NROWS_EMBED (BATCH*NPATCH)  // 4096
#define NHEAD   384

// ---------------------------------------------------------------------------
// Scratch (device globals)
// ---------------------------------------------------------------------------
__device__ float g_patches[NROWS_EMBED * PD];
__device__ float g_x[NT * DMODEL];
__device__ float g_xn[NT * DMODEL];
__device__ float g_feat[NT * 3 * DMODEL];
__device__ float g_o[NT * DMODEL];
__device__ float g_hmid[NT * MLP];
__device__ float g_lb[DEPTH * DMODEL];
__device__ float g_cls[BATCH * DMODEL];

// ---------------------------------------------------------------------------
// Helpers
// ---------------------------------------------------------------------------
__device__ __forceinline__ uint32_t smem_u32(const void* p) {
    uint32_t a;
    asm("{ .reg .u64 t; cvta.to.shared.u64 t, %1; cvt.u32.u64 %0, t; }"
        : "=r"(a) : "l"(p));
    return a;
}

__device__ __forceinline__ void ldsm4(uint32_t* r, uint32_t addr) {
    asm volatile("ldmatrix.sync.aligned.m8n8.x4.shared.b16 {%0,%1,%2,%3}, [%4];"
                 : "=r"(r[0]), "=r"(r[1]), "=r"(r[2]), "=r"(r[3]) : "r"(addr));
}
__device__ __forceinline__ void ldsm4t(uint32_t* r, uint32_t addr) {
    asm volatile("ldmatrix.sync.aligned.m8n8.x4.trans.shared.b16 {%0,%1,%2,%3}, [%4];"
                 : "=r"(r[0]), "=r"(r[1]), "=r"(r[2]), "=r"(r[3]) : "r"(addr));
}
__device__ __forceinline__ void mma16816(float* d, const uint32_t* a, const uint32_t* b) {
    asm volatile(
        "mma.sync.aligned.m16n8k16.row.col.f32.bf16.bf16.f32 "
        "{%0,%1,%2,%3}, {%4,%5,%6,%7}, {%8,%9}, {%0,%1,%2,%3};"
        : "+f"(d[0]), "+f"(d[1]), "+f"(d[2]), "+f"(d[3])
        : "r"(a[0]), "r"(a[1]), "r"(a[2]), "r"(a[3]), "r"(b[0]), "r"(b[1]));
}

__device__ __forceinline__ float gelu_exact(float x) {
    return 0.5f * x * (1.f + erff(x * 0.70710678118654752440f));
}

__device__ __forceinline__ float blockReduceSum(float v) {
    __shared__ float sh[32];
    __shared__ float res;
    int lane = threadIdx.x & 31;
    int wid  = threadIdx.x >> 5;
    #pragma unroll
    for (int o = 16; o > 0; o >>= 1) v += __shfl_down_sync(0xffffffffu, v, o);
    if (lane == 0) sh[wid] = v;
    __syncthreads();
    int nw = (blockDim.x + 31) >> 5;
    v = (threadIdx.x < nw) ? sh[threadIdx.x] : 0.f;
    if (wid == 0) {
        #pragma unroll
        for (int o = 16; o > 0; o >>= 1) v += __shfl_down_sync(0xffffffffu, v, o);
        if (lane == 0) res = v;
    }
    __syncthreads();
    return res;
}

// fp32 -> (hi, lo) bf16
__device__ __forceinline__ void f2bf2(float v, uint32_t& h, uint32_t& l) {
    __nv_bfloat16 bh = __float2bfloat16_rn(v);
    float r = v - __bfloat162float(bh);
    __nv_bfloat16 bl = __float2bfloat16_rn(r);
    h = (uint32_t)__bfloat16_as_ushort(bh);
    l = (uint32_t)__bfloat16_as_ushort(bl);
}
__device__ __forceinline__ void cvt4(float4 v, uint2& h, uint2& l) {
    uint32_t h0,l0,h1,l1,h2,l2,h3,l3;
    f2bf2(v.x, h0, l0); f2bf2(v.y, h1, l1);
    f2bf2(v.z, h2, l2); f2bf2(v.w, h3, l3);
    h = make_uint2(h0 | (h1 << 16), h2 | (h3 << 16));
    l = make_uint2(l0 | (l1 << 16), l2 | (l3 << 16));
}

// ---------------------------------------------------------------------------
// HMMA GEMM: C[M,N] = A[M,K] * B[K,N], bf16 hi/lo 3-pass, fp32 reg accum.
// CTA tile 128x128, K-chunk 32, 8 warps (2m x 4n), warp tile 64x32.
// Requires K%32==0, N%128==0. M arbitrary.
// ---------------------------------------------------------------------------
#define EPI_STORE      0
#define EPI_EMBED      1
#define EPI_RESID      2
#define EPI_BIAS_GELU  3
#define EPI_BIAS_RESID 4

#define APITCH 80      // bytes per A smem row (32 bf16 + 8 pad)
#define BPITCH 272     // bytes per B smem row (128 bf16 + 8 pad)
#define OFF_AH 0
#define OFF_AL 10240   // 128*80
#define OFF_BH 20480
#define OFF_BL 29184   // 20480 + 32*272
#define SBUF   37888   // 29184 + 32*272
#define SMTOT  (2*SBUF)

__device__ __forceinline__ void gload(const float* __restrict__ A,
                                      const float* __restrict__ B,
                                      int M, int N, int K,
                                      int rowBase, int colBase, int c, int tid,
                                      float4* ra, float4* rb)
{
    const int k0 = c << 5;
    #pragma unroll
    for (int i = 0; i < 4; i++) {
        int idx = tid + i * 256;
        int r   = idx >> 3;
        int k4  = (idx & 7) << 2;
        int gr  = rowBase + r;
        if (gr < M) ra[i] = *reinterpret_cast<const float4*>(A + (size_t)gr * K + k0 + k4);
        else        ra[i] = make_float4(0.f, 0.f, 0.f, 0.f);
        int bk = idx >> 5;
        int n4 = (idx & 31) << 2;
        rb[i] = *reinterpret_cast<const float4*>(B + (size_t)(k0 + bk) * N + colBase + n4);
    }
}

__device__ __forceinline__ void store_cvt(char* sb, int tid,
                                          const float4* ra, const float4* rb)
{
    #pragma unroll
    for (int i = 0; i < 4; i++) {
        int idx = tid + i * 256;
        int r   = idx >> 3;
        int k4  = (idx & 7) << 2;
        uint2 h, l;
        cvt4(ra[i], h, l);
        uint32_t off = (uint32_t)(r * APITCH + (k4 << 1));
        *reinterpret_cast<uint2*>(sb + OFF_AH + off) = h;
        *reinterpret_cast<uint2*>(sb + OFF_AL + off) = l;
        int bk = idx >> 5;
        int n4 = (idx & 31) << 2;
        cvt4(rb[i], h, l);
        uint32_t boff = (uint32_t)(bk * BPITCH + (n4 << 1));
        *reinterpret_cast<uint2*>(sb + OFF_BH + boff) = h;
        *reinterpret_cast<uint2*>(sb + OFF_BL + boff) = l;
    }
}

__device__ __forceinline__ void compute_chunk(uint32_t sbuf, int lane, int wm, int wn,
                                              float acc[4][4][4])
{
    #pragma unroll
    for (int k16 = 0; k16 < 32; k16 += 16) {
        uint32_t aH[4][4], aL[4][4], bH[2][4], bL[2][4];
        const uint32_t arow = (uint32_t)(wm + (lane & 7) + (lane & 8));
        const uint32_t aoff = arow * APITCH + (uint32_t)(k16 + ((lane & 16) >> 1)) * 2;
        #pragma unroll
        for (int mb = 0; mb < 4; mb++) {
            ldsm4(aH[mb], sbuf + OFF_AH + aoff + mb * 16 * APITCH);
            ldsm4(aL[mb], sbuf + OFF_AL + aoff + mb * 16 * APITCH);
        }
        const uint32_t brow = (uint32_t)(k16 + (lane & 7) + ((lane & 16) >> 1));
        const uint32_t boff = brow * BPITCH + (uint32_t)(wn + (lane & 8)) * 2;
        #pragma unroll
        for (int nb2 = 0; nb2 < 2; nb2++) {
            ldsm4t(bH[nb2], sbuf + OFF_BH + boff + nb2 * 32);
            ldsm4t(bL[nb2], sbuf + OFF_BL + boff + nb2 * 32);
        }
        #pragma unroll
        for (int mb = 0; mb < 4; mb++) {
            #pragma unroll
            for (int nb = 0; nb < 4; nb++) {
                uint32_t bh[2] = { bH[nb >> 1][nb & 1], bH[nb >> 1][(nb & 1) + 2] };
                uint32_t bl[2] = { bL[nb >> 1][nb & 1], bL[nb >> 1][(nb & 1) + 2] };
                mma16816(acc[mb][nb], aH[mb], bh);
                mma16816(acc[mb][nb], aH[mb], bl);
                mma16816(acc[mb][nb], aL[mb], bh);
            }
        }
    }
}

template<int EPI>
__global__ __launch_bounds__(256, 1)
void mmagemm_k(const float* __restrict__ A, const float* __restrict__ B,
               float* __restrict__ C, const float* __restrict__ bias,
               const float* __restrict__ extra, int M, int N, int K)
{
    extern __shared__ char smem[];
    const uint32_t sbase = smem_u32(smem);
    const int tid  = threadIdx.x;
    const int lane = tid & 31;
    const int wid  = tid >> 5;
    const int wm   = (wid >> 2) * 64;
    const int wn   = (wid & 3) * 32;
    const int rowBase = blockIdx.y * 128;
    const int colBase = blockIdx.x * 128;
    const int nc = K >> 5;

    float acc[4][4][4];
    #pragma unroll
    for (int a = 0; a < 4; a++)
        #pragma unroll
        for (int b = 0; b < 4; b++)
            #pragma unroll
            for (int c = 0; c < 4; c++) acc[a][b][c] = 0.f;

    float4 ra[4], rb[4];
    gload(A, B, M, N, K, rowBase, colBase, 0, tid, ra, rb);
    store_cvt(smem, tid, ra, rb);
    __syncthreads();

    for (int c = 0; c < nc; c++) {
        const int buf = c & 1;
        const bool more = (c + 1) < nc;
        if (more) gload(A, B, M, N, K, rowBase, colBase, c + 1, tid, ra, rb);
        compute_chunk(sbase + buf * SBUF, lane, wm, wn, acc);
        if (more) store_cvt(smem + (buf ^ 1) * SBUF, tid, ra, rb);
        __syncthreads();
    }

    // ---- epilogue ----
    const int mrow = rowBase + wm + (lane >> 2);
    const int mcol = colBase + wn + (lane & 3) * 2;
    #pragma unroll
    for (int mi = 0; mi < 4; mi++) {
        #pragma unroll
        for (int hf = 0; hf < 2; hf++) {
            const int row = mrow + mi * 16 + hf * 8;
            if (row >= M) continue;
            #pragma unroll
            for (int ni = 0; ni < 4; ni++) {
                const int col = mcol + ni * 8;
                float v0 = acc[mi][ni][hf * 2];
                float v1 = acc[mi][ni][hf * 2 + 1];
                if (EPI == EPI_STORE) {
                    *reinterpret_cast<float2*>(C + (size_t)row * N + col) =
                        make_float2(v0, v1);
                } else if (EPI == EPI_EMBED) {
                    int b  = row >> 8;
                    int tl = row & 255;
                    float2 bb = *reinterpret_cast<const float2*>(bias + col);
                    float2 pp = *reinterpret_cast<const float2*>(extra + (size_t)(tl + 1) * N + col);
                    *reinterpret_cast<float2*>(C + ((size_t)b * TTOK + 1 + tl) * N + col) =
                        make_float2(v0 + bb.x + pp.x, v1 + bb.y + pp.y);
                } else if (EPI == EPI_RESID) {
                    float2* o = reinterpret_cast<float2*>(C + (size_t)row * N + col);
                    float2 cc = *o;
                    *o = make_float2(cc.x + v0, cc.y + v1);
                } else if (EPI == EPI_BIAS_GELU) {
                    float2 bb = *reinterpret_cast<const float2*>(bias + col);
                    *reinterpret_cast<float2*>(C + (size_t)row * N + col) =
                        make_float2(gelu_exact(v0 + bb.x), gelu_exact(v1 + bb.y));
                } else if (EPI == EPI_BIAS_RESID) {
                    float2 bb = *reinterpret_cast<const float2*>(bias + col);
                    float2* o = reinterpret_cast<float2*>(C + (size_t)row * N + col);
                    float2 cc = *o;
                    *o = make_float2(cc.x + v0 + bb.x, cc.y + v1 + bb.y);
                }
            }
        }
    }
}

// ---------------------------------------------------------------------------
// Shifted-patch extraction + LayerNorm
// ---------------------------------------------------------------------------
__global__ __launch_bounds__(256)
void patchln_k(const float* __restrict__ img,
               const float* __restrict__ ln_g,
               const float* __restrict__ ln_b,
               float* __restrict__ out)
{
    const int blk = blockIdx.x;
    const int b   = blk >> 8;
    const int pt  = blk & 255;
    const int ph  = pt >> 4;
    const int pw  = pt & 15;

    __shared__ float vals[PD];

    const int sh_tab[5] = {0, 0, 0, 1, -1};
    const int sw_tab[5] = {0, 1, -1, 0, 0};

    float s = 0.f, ss = 0.f;
    for (int f = threadIdx.x; f < PD; f += 256) {
        int py  = f / (PSZ * C5);
        int rem = f - py * (PSZ * C5);
        int px  = rem / C5;
        int c   = rem - px * C5;
        int g   = c / CIN;
        int ch  = c - g * CIN;
        int row = ph * PSZ + py - sh_tab[g];
        int col = pw * PSZ + px - sw_tab[g];
        float v = 0.f;
        if (row >= 0 && row < IMG && col >= 0 && col < IMG)
            v = img[(((long)b * CIN + ch) * IMG + row) * IMG + col];
        vals[f] = v;
        s  += v;
        ss += v * v;
    }
    float tsum  = blockReduceSum(s);
    float tsum2 = blockReduceSum(ss);
    float mean  = tsum * (1.f / PD);
    float var   = tsum2 * (1.f / PD) - mean * mean;
    float rstd  = rsqrtf(var + 1e-5f);
    __syncthreads();
    float* orow = out + (long)blk * PD;
    for (int f = threadIdx.x; f < PD; f += 256)
        orow[f] = (vals[f] - mean) * rstd * ln_g[f] + ln_b[f];
}

__global__ void lb_k(const float* __restrict__ lbin, float* __restrict__ lbout)
{
    int d = blockIdx.x * blockDim.x + threadIdx.x;
    if (d >= DMODEL) return;
    float v[DEPTH];
    float m = -1e30f;
    #pragma unroll
    for (int i = 0; i < DEPTH; i++) { v[i] = lbin[i * DMODEL + d]; m = fmaxf(m, v[i]); }
    float s = 0.f;
    #pragma unroll
    for (int i = 0; i < DEPTH; i++) { v[i] = expf(v[i] - m); s += v[i]; }
    float inv = 1.f / s;
    float c = 0.f;
    float c0 = v[0] * inv;
    #pragma unroll
    for (int i = 0; i < DEPTH; i++) { c += v[i] * inv; lbout[i * DMODEL + d] = c - c0; }
}

__global__ void cls_k(const float* __restrict__ cls_token,
                      const float* __restrict__ pos,
                      float* __restrict__ x)
{
    int i = blockIdx.x * blockDim.x + threadIdx.x;
    if (i >= BATCH * DMODEL) return;
    int b = i / DMODEL, d = i - b * DMODEL;
    x[(long)b * TTOK * DMODEL + d] = cls_token[d] + pos[d];
}

__global__ __launch_bounds__(256)
void rmsnorm_k(const float* __restrict__ x, float* __restrict__ y)
{
    const long row = blockIdx.x;
    const float* xr = x + row * DMODEL;
    float s = 0.f;
    for (int i = threadIdx.x; i < DMODEL; i += 256) { float v = xr[i]; s += v * v; }
    float tot = blockReduceSum(s);
    float r = rsqrtf(tot * (1.f / DMODEL) + 1e-6f);
    float* yr = y + row * DMODEL;
    for (int i = threadIdx.x; i < DMODEL; i += 256) yr[i] = xr[i] * r;
}

__global__ __launch_bounds__(256)
void hgru_k(const float* __restrict__ feat, const float* __restrict__ lb,
            float* __restrict__ o)
{
    int e = blockIdx.x * blockDim.x + threadIdx.x;
    if (e >= TTOK * NHEAD) return;
    int t = e / NHEAD;
    int h = e - t * NHEAD;

    float lb0 = lb[2 * h];
    float lb1 = lb[2 * h + 1];
    float S00 = 0.f, S01 = 0.f, S10 = 0.f, S11 = 0.f;

    #pragma unroll 1
    for (int n = 0; n < BATCH; n++) {
        const float* r = feat + (long)(n * TTOK + t) * (3 * DMODEL);
        float2 vv = *(const float2*)(r + 2 * h);
        float2 qq = *(const float2*)(r + DMODEL + 2 * h);
        float2 ff = *(const float2*)(r + 2 * DMODEL + 2 * h);
        float v0 = gelu_exact(vv.x), v1 = gelu_exact(vv.y);
        float q0 = gelu_exact(qq.x), q1 = gelu_exact(qq.y);
        float s0 = 1.f / (1.f + expf(-ff.x));
        float s1 = 1.f / (1.f + expf(-ff.y));
        float lam0 = lb0 + (1.f - lb0) * s0;
        float lam1 = lb1 + (1.f - lb1) * s1;
        float k0 = 1.f - lam0, k1 = 1.f - lam1;
        S00 = lam0 * S00 + k0 * v0;  S01 = lam0 * S01 + k0 * v1;
        S10 = lam1 * S10 + k1 * v0;  S11 = lam1 * S11 + k1 * v1;
        float o0 = q0 * S00 + q1 * S10;
        float o1 = q0 * S01 + q1 * S11;
        *(float2*)(o + (long)(n * TTOK + t) * DMODEL + 2 * h) = make_float2(o0, o1);
    }
}

__global__ __launch_bounds__(256)
void final_k(const float* __restrict__ x,
             const float* __restrict__ g, const float* __restrict__ bvec,
             float* __restrict__ cls)
{
    int b = blockIdx.x;
    const float* xr = x + (long)b * TTOK * DMODEL;
    __shared__ float y[DMODEL];
    float s = 0.f, ss = 0.f;
    for (int i = threadIdx.x; i < DMODEL; i += 256) {
        float v = xr[i];
        y[i] = v;
        s  += v;
        ss += v * v;
    }
    float tsum  = blockReduceSum(s);
    float tsum2 = blockReduceSum(ss);
    float rstd1 = rsqrtf(tsum2 * (1.f / DMODEL) + 1e-6f);
    float mean  = rstd1 * tsum * (1.f / DMODEL);
    float ez2   = rstd1 * rstd1 * tsum2 * (1.f / DMODEL);
    float var   = ez2 - mean * mean;
    float rstd2 = rsqrtf(var + 1e-5f);
    __syncthreads();
    for (int i = threadIdx.x; i < DMODEL; i += 256) {
        float z = y[i] * rstd1;
        cls[(long)b * DMODEL + i] = (z - mean) * rstd2 * g[i] + bvec[i];
    }
}

__global__ __launch_bounds__(256)
void head_k(const float* __restrict__ cls, const float* __restrict__ w,
            const float* __restrict__ bias, float* __restrict__ out)
{
    int idx = blockIdx.x * blockDim.x + threadIdx.x;
    if (idx >= BATCH * NCLS) return;
    int b = idx / NCLS, c = idx - b * NCLS;
    const float* xr = cls + (long)b * DMODEL;
    float s = bias[c];
    #pragma unroll 4
    for (int k = 0; k < DMODEL; k++)
        s = fmaf(xr[k], w[(long)k * NCLS + c], s);
    out[idx] = s;
}

// ---------------------------------------------------------------------------
// Launch
// ---------------------------------------------------------------------------
extern "C" void kernel_launch(void* const* d_in, const int* in_sizes, int n_in,
                              void* d_out, int out_size)
{
    const float* img          = (const float*)d_in[0];
    const float* spt_ln_g     = (const float*)d_in[1];
    const float* spt_ln_b     = (const float*)d_in[2];
    const float* spt_w        = (const float*)d_in[3];
    const float* spt_b        = (const float*)d_in[4];
    const float* pos_emb      = (const float*)d_in[5];
    const float* cls_token    = (const float*)d_in[6];
    const float* lower_bounds = (const float*)d_in[7];
    const float* in_proj_w    = (const float*)d_in[8];
    const float* out_proj_w   = (const float*)d_in[9];
    const float* ff_w1        = (const float*)d_in[10];
    const float* ff_b1        = (const float*)d_in[11];
    const float* ff_w2        = (const float*)d_in[12];
    const float* ff_b2        = (const float*)d_in[13];
    const float* head_ln_g    = (const float*)d_in[14];
    const float* head_ln_b    = (const float*)d_in[15];
    const float* head_w       = (const float*)d_in[16];
    const float* head_b       = (const float*)d_in[17];

    float *patches, *x, *xn, *feat, *o, *hmid, *lb, *cls;
    cudaGetSymbolAddress((void**)&patches, g_patches);
    cudaGetSymbolAddress((void**)&x,       g_x);
    cudaGetSymbolAddress((void**)&xn,      g_xn);
    cudaGetSymbolAddress((void**)&feat,    g_feat);
    cudaGetSymbolAddress((void**)&o,       g_o);
    cudaGetSymbolAddress((void**)&hmid,    g_hmid);
    cudaGetSymbolAddress((void**)&lb,      g_lb);
    cudaGetSymbolAddress((void**)&cls,     g_cls);

    static bool attr_done = false;
    if (!attr_done) {
        cudaFuncSetAttribute(mmagemm_k<EPI_STORE>,      cudaFuncAttributeMaxDynamicSharedMemorySize, SMTOT);
        cudaFuncSetAttribute(mmagemm_k<EPI_EMBED>,      cudaFuncAttributeMaxDynamicSharedMemorySize, SMTOT);
        cudaFuncSetAttribute(mmagemm_k<EPI_RESID>,      cudaFuncAttributeMaxDynamicSharedMemorySize, SMTOT);
        cudaFuncSetAttribute(mmagemm_k<EPI_BIAS_GELU>,  cudaFuncAttributeMaxDynamicSharedMemorySize, SMTOT);
        cudaFuncSetAttribute(mmagemm_k<EPI_BIAS_RESID>, cudaFuncAttributeMaxDynamicSharedMemorySize, SMTOT);
        attr_done = true;
    }

    patchln_k<<<NROWS_EMBED, 256>>>(img, spt_ln_g, spt_ln_b, patches);
    lb_k<<<(DMODEL + 255) / 256, 256>>>(lower_bounds, lb);
    cls_k<<<(BATCH * DMODEL + 255) / 256, 256>>>(cls_token, pos_emb, x);

    {
        dim3 grid(DMODEL / 128, (NROWS_EMBED + 127) / 128);
        mmagemm_k<EPI_EMBED><<<grid, 256, SMTOT>>>(patches, spt_w, x, spt_b, pos_emb,
                                                   NROWS_EMBED, DMODEL, PD);
    }

    for (int i = 0; i < DEPTH; i++) {
        rmsnorm_k<<<NT, 256>>>(x, xn);
        {
            dim3 grid((3 * DMODEL) / 128, (NT + 127) / 128);
            mmagemm_k<EPI_STORE><<<grid, 256, SMTOT>>>(
                xn, in_proj_w + (long)i * DMODEL * 3 * DMODEL,
                feat, nullptr, nullptr, NT, 3 * DMODEL, DMODEL);
        }
        hgru_k<<<(TTOK * NHEAD + 255) / 256, 256>>>(feat, lb + (long)i * DMODEL, o);
        {
            dim3 grid(DMODEL / 128, (NT + 127) / 128);
            mmagemm_k<EPI_RESID><<<grid, 256, SMTOT>>>(
                o, out_proj_w + (long)i * DMODEL * DMODEL,
                x, nullptr, nullptr, NT, DMODEL, DMODEL);
        }
        rmsnorm_k<<<NT, 256>>>(x, xn);
        {
            dim3 grid(MLP / 128, (NT + 127) / 128);
            mmagemm_k<EPI_BIAS_GELU><<<grid, 256, SMTOT>>>(
                xn, ff_w1 + (long)i * DMODEL * MLP,
                hmid, ff_b1 + (long)i * MLP, nullptr, NT, MLP, DMODEL);
        }
        {
            dim3 grid(DMODEL / 128, (NT + 127) / 128);
            mmagemm_k<EPI_BIAS_RESID><<<grid, 256, SMTOT>>>(
                hmid, ff_w2 + (long)i * MLP * DMODEL,
                x, ff_b2 + (long)i * DMODEL, nullptr, NT, DMODEL, MLP);
        }
    }

    final_k<<<BATCH, 256>>>(x, head_ln_g, head_ln_b, cls);
    head_k<<<(BATCH * NCLS + 255) / 256, 256>>>(cls, head_w, head_b, (float*)d_out);
}

// round 4
// speedup vs baseline: 2.4000x; 1.1500x over previous
#include <cuda_runtime.h>
#include <cuda_bf16.h>
#include <math.h>
#include <stdint.h>

// ---------------------------------------------------------------------------
// Problem constants
// ---------------------------------------------------------------------------
#define BATCH   16
#define CIN     3
#define IMG     256
#define PSZ     16
#define NPATCH  256
#define C5      15
#define PD      3840
#define DMODEL  768
#define DEPTH   8
#define MLP     3072
#define NCLS    1000
#define TTOK    257
#define NT      (BATCH*TTOK)        // 4112
#define NROWS_EMBED (BATCH*NPATCH)  // 4096
#define NHEAD   384

// weight plane offsets (elements)
#define WOFF_SPT  0
#define WSZ_SPT   (PD*DMODEL)                      // 2,949,120
#define WOFF_INP  (WOFF_SPT + WSZ_SPT)
#define WSZ_INP   (DEPTH*DMODEL*3*DMODEL)          // 14,155,776
#define WOFF_OUTP (WOFF_INP + WSZ_INP)
#define WSZ_OUTP  (DEPTH*DMODEL*DMODEL)            // 4,718,592
#define WOFF_FF1  (WOFF_OUTP + WSZ_OUTP)
#define WSZ_FF1   (DEPTH*DMODEL*MLP)               // 18,874,368
#define WOFF_FF2  (WOFF_FF1 + WSZ_FF1)
#define WSZ_FF2   (DEPTH*MLP*DMODEL)               // 18,874,368
#define WTOT      (WOFF_FF2 + WSZ_FF2)             // 59,572,224

// ---------------------------------------------------------------------------
// Scratch (device globals)
// ---------------------------------------------------------------------------
__device__ __nv_bfloat16 g_wh[WTOT];
__device__ __nv_bfloat16 g_wl[WTOT];
__device__ __nv_bfloat16 g_ph[NROWS_EMBED * PD];
__device__ __nv_bfloat16 g_pl[NROWS_EMBED * PD];
__device__ __nv_bfloat16 g_xnh[NT * DMODEL];
__device__ __nv_bfloat16 g_xnl[NT * DMODEL];
__device__ __nv_bfloat16 g_oh[NT * DMODEL];
__device__ __nv_bfloat16 g_ol[NT * DMODEL];
__device__ __nv_bfloat16 g_hmh[NT * MLP];
__device__ __nv_bfloat16 g_hml[NT * MLP];
__device__ float g_x[NT * DMODEL];
__device__ float g_feat[NT * 3 * DMODEL];
__device__ float g_lb[DEPTH * DMODEL];
__device__ float g_cls[BATCH * DMODEL];

// ---------------------------------------------------------------------------
// Helpers
// ---------------------------------------------------------------------------
__device__ __forceinline__ uint32_t smem_u32(const void* p) {
    uint32_t a;
    asm("{ .reg .u64 t; cvta.to.shared.u64 t, %1; cvt.u32.u64 %0, t; }"
        : "=r"(a) : "l"(p));
    return a;
}
__device__ __forceinline__ void ldsm4(uint32_t* r, uint32_t addr) {
    asm volatile("ldmatrix.sync.aligned.m8n8.x4.shared.b16 {%0,%1,%2,%3}, [%4];"
                 : "=r"(r[0]), "=r"(r[1]), "=r"(r[2]), "=r"(r[3]) : "r"(addr));
}
__device__ __forceinline__ void ldsm4t(uint32_t* r, uint32_t addr) {
    asm volatile("ldmatrix.sync.aligned.m8n8.x4.trans.shared.b16 {%0,%1,%2,%3}, [%4];"
                 : "=r"(r[0]), "=r"(r[1]), "=r"(r[2]), "=r"(r[3]) : "r"(addr));
}
__device__ __forceinline__ void mma16816(float* d, const uint32_t* a, const uint32_t* b) {
    asm volatile(
        "mma.sync.aligned.m16n8k16.row.col.f32.bf16.bf16.f32 "
        "{%0,%1,%2,%3}, {%4,%5,%6,%7}, {%8,%9}, {%0,%1,%2,%3};"
        : "+f"(d[0]), "+f"(d[1]), "+f"(d[2]), "+f"(d[3])
        : "r"(a[0]), "r"(a[1]), "r"(a[2]), "r"(a[3]), "r"(b[0]), "r"(b[1]));
}
__device__ __forceinline__ void cpasync16(uint32_t dst, const void* src, uint32_t n) {
    asm volatile("cp.async.cg.shared.global [%0], [%1], 16, %2;"
                 :: "r"(dst), "l"(src), "r"(n) : "memory");
}
__device__ __forceinline__ void cp_commit() {
    asm volatile("cp.async.commit_group;" ::: "memory");
}
template<int N>
__device__ __forceinline__ void cp_wait() {
    asm volatile("cp.async.wait_group %0;" :: "n"(N) : "memory");
}

__device__ __forceinline__ float gelu_exact(float x) {
    return 0.5f * x * (1.f + erff(x * 0.70710678118654752440f));
}

__device__ __forceinline__ float blockReduceSum(float v) {
    __shared__ float sh[32];
    __shared__ float res;
    int lane = threadIdx.x & 31;
    int wid  = threadIdx.x >> 5;
    #pragma unroll
    for (int o = 16; o > 0; o >>= 1) v += __shfl_down_sync(0xffffffffu, v, o);
    if (lane == 0) sh[wid] = v;
    __syncthreads();
    int nw = (blockDim.x + 31) >> 5;
    v = (threadIdx.x < nw) ? sh[threadIdx.x] : 0.f;
    if (wid == 0) {
        #pragma unroll
        for (int o = 16; o > 0; o >>= 1) v += __shfl_down_sync(0xffffffffu, v, o);
        if (lane == 0) res = v;
    }
    __syncthreads();
    return res;
}

// fp32 -> (hi, lo) bf16
__device__ __forceinline__ void f2bf2(float v, uint32_t& h, uint32_t& l) {
    __nv_bfloat16 bh = __float2bfloat16_rn(v);
    float r = v - __bfloat162float(bh);
    __nv_bfloat16 bl = __float2bfloat16_rn(r);
    h = (uint32_t)__bfloat16_as_ushort(bh);
    l = (uint32_t)__bfloat16_as_ushort(bl);
}
__device__ __forceinline__ void cvt4(float4 v, uint2& h, uint2& l) {
    uint32_t h0,l0,h1,l1,h2,l2,h3,l3;
    f2bf2(v.x, h0, l0); f2bf2(v.y, h1, l1);
    f2bf2(v.z, h2, l2); f2bf2(v.w, h3, l3);
    h = make_uint2(h0 | (h1 << 16), h2 | (h3 << 16));
    l = make_uint2(l0 | (l1 << 16), l2 | (l3 << 16));
}

// ---------------------------------------------------------------------------
// Weight pre-conversion: fp32 -> bf16 hi/lo planes
// ---------------------------------------------------------------------------
__global__ __launch_bounds__(256)
void cvtw_k(const float* __restrict__ x, __nv_bfloat16* __restrict__ h,
            __nv_bfloat16* __restrict__ l, int n)
{
    int i = (blockIdx.x * blockDim.x + threadIdx.x) * 4;
    if (i >= n) return;
    float4 v = *reinterpret_cast<const float4*>(x + i);
    uint2 hh, ll;
    cvt4(v, hh, ll);
    *reinterpret_cast<uint2*>(h + i) = hh;
    *reinterpret_cast<uint2*>(l + i) = ll;
}

// ---------------------------------------------------------------------------
// HMMA GEMM, bf16 hi/lo 3-pass, cp.async 4-stage pipeline.
// CTA tile 128x128, K-chunk 32, 8 warps (2m x 4n), warp tile 64x32.
// ---------------------------------------------------------------------------
#define EPI_STORE       0   // feat fp32
#define EPI_EMBED       1
#define EPI_RESID       2
#define EPI_GELU_PLANES 3   // write bf16 hi/lo planes of gelu(acc+bias)
#define EPI_BIAS_RESID  4

#define APITCH 80
#define BPITCH 272
#define OFF_AH 0
#define OFF_AL 10240
#define OFF_BH 20480
#define OFF_BL 29184
#define SBUF   37888
#define STAGES 4
#define SMTOT  (STAGES*SBUF)   // 151552

__device__ __forceinline__ void stage_load(uint32_t sb,
                                           const __nv_bfloat16* __restrict__ Ah,
                                           const __nv_bfloat16* __restrict__ Al,
                                           const __nv_bfloat16* __restrict__ Bh,
                                           const __nv_bfloat16* __restrict__ Bl,
                                           int M, int N, int K,
                                           int rowBase, int colBase, int s, int tid)
{
    const int k0 = s << 5;
    #pragma unroll
    for (int i = 0; i < 2; i++) {
        int chunk = tid + i * 256;
        int row = chunk >> 2;
        int seg = chunk & 3;
        int gr  = rowBase + row;
        uint32_t nbytes = (gr < M) ? 16u : 0u;
        int grs = (gr < M) ? gr : (M - 1);
        size_t goff = (size_t)grs * K + k0 + seg * 8;
        uint32_t so = (uint32_t)(row * APITCH + seg * 16);
        cpasync16(sb + OFF_AH + so, Ah + goff, nbytes);
        cpasync16(sb + OFF_AL + so, Al + goff, nbytes);
    }
    #pragma unroll
    for (int i = 0; i < 2; i++) {
        int chunk = tid + i * 256;
        int row = chunk >> 4;
        int seg = chunk & 15;
        size_t goff = (size_t)(k0 + row) * N + colBase + seg * 8;
        uint32_t so = (uint32_t)(row * BPITCH + seg * 16);
        cpasync16(sb + OFF_BH + so, Bh + goff, 16u);
        cpasync16(sb + OFF_BL + so, Bl + goff, 16u);
    }
}

__device__ __forceinline__ void compute_chunk(uint32_t sbuf, int lane, int wm, int wn,
                                              float acc[4][4][4])
{
    #pragma unroll
    for (int k16 = 0; k16 < 32; k16 += 16) {
        uint32_t aH[4][4], aL[4][4], bH[2][4], bL[2][4];
        const uint32_t arow = (uint32_t)(wm + (lane & 7) + (lane & 8));
        const uint32_t aoff = arow * APITCH + (uint32_t)(k16 + ((lane & 16) >> 1)) * 2;
        #pragma unroll
        for (int mb = 0; mb < 4; mb++) {
            ldsm4(aH[mb], sbuf + OFF_AH + aoff + mb * 16 * APITCH);
            ldsm4(aL[mb], sbuf + OFF_AL + aoff + mb * 16 * APITCH);
        }
        const uint32_t brow = (uint32_t)(k16 + (lane & 7) + ((lane & 16) >> 1));
        const uint32_t boff = brow * BPITCH + (uint32_t)(wn + (lane & 8)) * 2;
        #pragma unroll
        for (int nb2 = 0; nb2 < 2; nb2++) {
            ldsm4t(bH[nb2], sbuf + OFF_BH + boff + nb2 * 32);
            ldsm4t(bL[nb2], sbuf + OFF_BL + boff + nb2 * 32);
        }
        #pragma unroll
        for (int mb = 0; mb < 4; mb++) {
            #pragma unroll
            for (int nb = 0; nb < 4; nb++) {
                uint32_t bh[2] = { bH[nb >> 1][nb & 1], bH[nb >> 1][(nb & 1) + 2] };
                uint32_t bl[2] = { bL[nb >> 1][nb & 1], bL[nb >> 1][(nb & 1) + 2] };
                mma16816(acc[mb][nb], aH[mb], bh);
                mma16816(acc[mb][nb], aH[mb], bl);
                mma16816(acc[mb][nb], aL[mb], bh);
            }
        }
    }
}

template<int EPI>
__global__ __launch_bounds__(256, 1)
void mmagemm_k(const __nv_bfloat16* __restrict__ Ah, const __nv_bfloat16* __restrict__ Al,
               const __nv_bfloat16* __restrict__ Bh, const __nv_bfloat16* __restrict__ Bl,
               void* __restrict__ Cv, void* __restrict__ C2v,
               const float* __restrict__ bias, const float* __restrict__ extra,
               int M, int N, int K)
{
    extern __shared__ char smem[];
    const uint32_t sbase = smem_u32(smem);
    const int tid  = threadIdx.x;
    const int lane = tid & 31;
    const int wid  = tid >> 5;
    const int wm   = (wid >> 2) * 64;
    const int wn   = (wid & 3) * 32;
    const int rowBase = blockIdx.y * 128;
    const int colBase = blockIdx.x * 128;
    const int nc = K >> 5;

    float acc[4][4][4];
    #pragma unroll
    for (int a = 0; a < 4; a++)
        #pragma unroll
        for (int b = 0; b < 4; b++)
            #pragma unroll
            for (int c = 0; c < 4; c++) acc[a][b][c] = 0.f;

    // prologue: commit STAGES-1 groups (loads or empties)
    #pragma unroll
    for (int s = 0; s < STAGES - 1; s++) {
        if (s < nc)
            stage_load(sbase + s * SBUF, Ah, Al, Bh, Bl, M, N, K, rowBase, colBase, s, tid);
        cp_commit();
    }

    for (int c = 0; c < nc; c++) {
        cp_wait<STAGES - 2>();
        __syncthreads();
        // commit stage c+STAGES-1 (writes buffer (c-1)%STAGES, free since last iter)
        int s = c + STAGES - 1;
        if (s < nc)
            stage_load(sbase + (s % STAGES) * SBUF, Ah, Al, Bh, Bl, M, N, K,
                       rowBase, colBase, s, tid);
        cp_commit();
        compute_chunk(sbase + (c % STAGES) * SBUF, lane, wm, wn, acc);
    }

    // ---- epilogue ----
    const int mrow = rowBase + wm + (lane >> 2);
    const int mcol = colBase + wn + (lane & 3) * 2;
    #pragma unroll
    for (int mi = 0; mi < 4; mi++) {
        #pragma unroll
        for (int hf = 0; hf < 2; hf++) {
            const int row = mrow + mi * 16 + hf * 8;
            if (row >= M) continue;
            #pragma unroll
            for (int ni = 0; ni < 4; ni++) {
                const int col = mcol + ni * 8;
                float v0 = acc[mi][ni][hf * 2];
                float v1 = acc[mi][ni][hf * 2 + 1];
                if (EPI == EPI_STORE) {
                    float* C = (float*)Cv;
                    *reinterpret_cast<float2*>(C + (size_t)row * N + col) =
                        make_float2(v0, v1);
                } else if (EPI == EPI_EMBED) {
                    float* C = (float*)Cv;
                    int b  = row >> 8;
                    int tl = row & 255;
                    float2 bb = *reinterpret_cast<const float2*>(bias + col);
                    float2 pp = *reinterpret_cast<const float2*>(extra + (size_t)(tl + 1) * N + col);
                    *reinterpret_cast<float2*>(C + ((size_t)b * TTOK + 1 + tl) * N + col) =
                        make_float2(v0 + bb.x + pp.x, v1 + bb.y + pp.y);
                } else if (EPI == EPI_RESID) {
                    float* C = (float*)Cv;
                    float2* o = reinterpret_cast<float2*>(C + (size_t)row * N + col);
                    float2 cc = *o;
                    *o = make_float2(cc.x + v0, cc.y + v1);
                } else if (EPI == EPI_GELU_PLANES) {
                    __nv_bfloat16* Hh = (__nv_bfloat16*)Cv;
                    __nv_bfloat16* Hl = (__nv_bfloat16*)C2v;
                    float2 bb = *reinterpret_cast<const float2*>(bias + col);
                    float g0 = gelu_exact(v0 + bb.x);
                    float g1 = gelu_exact(v1 + bb.y);
                    uint32_t h0,l0,h1,l1;
                    f2bf2(g0, h0, l0); f2bf2(g1, h1, l1);
                    size_t off = (size_t)row * N + col;
                    *reinterpret_cast<uint32_t*>(Hh + off) = h0 | (h1 << 16);
                    *reinterpret_cast<uint32_t*>(Hl + off) = l0 | (l1 << 16);
                } else if (EPI == EPI_BIAS_RESID) {
                    float* C = (float*)Cv;
                    float2 bb = *reinterpret_cast<const float2*>(bias + col);
                    float2* o = reinterpret_cast<float2*>(C + (size_t)row * N + col);
                    float2 cc = *o;
                    *o = make_float2(cc.x + v0 + bb.x, cc.y + v1 + bb.y);
                }
            }
        }
    }
}

// ---------------------------------------------------------------------------
// Shifted-patch extraction + LayerNorm -> bf16 hi/lo planes
// ---------------------------------------------------------------------------
__global__ __launch_bounds__(256)
void patchln_k(const float* __restrict__ img,
               const float* __restrict__ ln_g,
               const float* __restrict__ ln_b,
               __nv_bfloat16* __restrict__ ph,
               __nv_bfloat16* __restrict__ pl)
{
    const int blk = blockIdx.x;
    const int b   = blk >> 8;
    const int pt  = blk & 255;
    const int phh = pt >> 4;
    const int pw  = pt & 15;

    __shared__ float vals[PD];

    const int sh_tab[5] = {0, 0, 0, 1, -1};
    const int sw_tab[5] = {0, 1, -1, 0, 0};

    float s = 0.f, ss = 0.f;
    for (int f = threadIdx.x; f < PD; f += 256) {
        int py  = f / (PSZ * C5);
        int rem = f - py * (PSZ * C5);
        int px  = rem / C5;
        int c   = rem - px * C5;
        int g   = c / CIN;
        int ch  = c - g * CIN;
        int row = phh * PSZ + py - sh_tab[g];
        int col = pw * PSZ + px - sw_tab[g];
        float v = 0.f;
        if (row >= 0 && row < IMG && col >= 0 && col < IMG)
            v = img[(((long)b * CIN + ch) * IMG + row) * IMG + col];
        vals[f] = v;
        s  += v;
        ss += v * v;
    }
    float tsum  = blockReduceSum(s);
    float tsum2 = blockReduceSum(ss);
    float mean  = tsum * (1.f / PD);
    float var   = tsum2 * (1.f / PD) - mean * mean;
    float rstd  = rsqrtf(var + 1e-5f);
    __syncthreads();
    size_t rowoff = (size_t)blk * PD;
    for (int f = threadIdx.x; f < PD; f += 256) {
        float y = (vals[f] - mean) * rstd * ln_g[f] + ln_b[f];
        uint32_t hh, ll;
        f2bf2(y, hh, ll);
        ph[rowoff + f] = __ushort_as_bfloat16((unsigned short)hh);
        pl[rowoff + f] = __ushort_as_bfloat16((unsigned short)ll);
    }
}

// ---------------------------------------------------------------------------
__global__ void lb_k(const float* __restrict__ lbin, float* __restrict__ lbout)
{
    int d = blockIdx.x * blockDim.x + threadIdx.x;
    if (d >= DMODEL) return;
    float v[DEPTH];
    float m = -1e30f;
    #pragma unroll
    for (int i = 0; i < DEPTH; i++) { v[i] = lbin[i * DMODEL + d]; m = fmaxf(m, v[i]); }
    float s = 0.f;
    #pragma unroll
    for (int i = 0; i < DEPTH; i++) { v[i] = expf(v[i] - m); s += v[i]; }
    float inv = 1.f / s;
    float c = 0.f;
    float c0 = v[0] * inv;
    #pragma unroll
    for (int i = 0; i < DEPTH; i++) { c += v[i] * inv; lbout[i * DMODEL + d] = c - c0; }
}

__global__ void cls_k(const float* __restrict__ cls_token,
                      const float* __restrict__ pos,
                      float* __restrict__ x)
{
    int i = blockIdx.x * blockDim.x + threadIdx.x;
    if (i >= BATCH * DMODEL) return;
    int b = i / DMODEL, d = i - b * DMODEL;
    x[(long)b * TTOK * DMODEL + d] = cls_token[d] + pos[d];
}

// RMSNorm -> bf16 hi/lo planes
__global__ __launch_bounds__(256)
void rmsnorm_k(const float* __restrict__ x,
               __nv_bfloat16* __restrict__ yh, __nv_bfloat16* __restrict__ yl)
{
    const long row = blockIdx.x;
    const float* xr = x + row * DMODEL;
    float s = 0.f;
    for (int i = threadIdx.x; i < DMODEL; i += 256) { float v = xr[i]; s += v * v; }
    float tot = blockReduceSum(s);
    float r = rsqrtf(tot * (1.f / DMODEL) + 1e-6f);
    size_t off = (size_t)row * DMODEL;
    for (int i = threadIdx.x; i < DMODEL; i += 256) {
        uint32_t hh, ll;
        f2bf2(xr[i] * r, hh, ll);
        yh[off + i] = __ushort_as_bfloat16((unsigned short)hh);
        yl[off + i] = __ushort_as_bfloat16((unsigned short)ll);
    }
}

// hGRU2 scan -> bf16 hi/lo planes
__global__ __launch_bounds__(256)
void hgru_k(const float* __restrict__ feat, const float* __restrict__ lb,
            __nv_bfloat16* __restrict__ oh, __nv_bfloat16* __restrict__ ol)
{
    int e = blockIdx.x * blockDim.x + threadIdx.x;
    if (e >= TTOK * NHEAD) return;
    int t = e / NHEAD;
    int h = e - t * NHEAD;

    float lb0 = lb[2 * h];
    float lb1 = lb[2 * h + 1];
    float S00 = 0.f, S01 = 0.f, S10 = 0.f, S11 = 0.f;

    #pragma unroll 1
    for (int n = 0; n < BATCH; n++) {
        const float* r = feat + (long)(n * TTOK + t) * (3 * DMODEL);
        float2 vv = *(const float2*)(r + 2 * h);
        float2 qq = *(const float2*)(r + DMODEL + 2 * h);
        float2 ff = *(const float2*)(r + 2 * DMODEL + 2 * h);
        float v0 = gelu_exact(vv.x), v1 = gelu_exact(vv.y);
        float q0 = gelu_exact(qq.x), q1 = gelu_exact(qq.y);
        float s0 = 1.f / (1.f + expf(-ff.x));
        float s1 = 1.f / (1.f + expf(-ff.y));
        float lam0 = lb0 + (1.f - lb0) * s0;
        float lam1 = lb1 + (1.f - lb1) * s1;
        float k0 = 1.f - lam0, k1 = 1.f - lam1;
        S00 = lam0 * S00 + k0 * v0;  S01 = lam0 * S01 + k0 * v1;
        S10 = lam1 * S10 + k1 * v0;  S11 = lam1 * S11 + k1 * v1;
        float o0 = q0 * S00 + q1 * S10;
        float o1 = q0 * S01 + q1 * S11;
        uint32_t h0,l0,h1,l1;
        f2bf2(o0, h0, l0); f2bf2(o1, h1, l1);
        size_t off = (size_t)(n * TTOK + t) * DMODEL + 2 * h;
        *reinterpret_cast<uint32_t*>(oh + off) = h0 | (h1 << 16);
        *reinterpret_cast<uint32_t*>(ol + off) = l0 | (l1 << 16);
    }
}

__global__ __launch_bounds__(256)
void final_k(const float* __restrict__ x,
             const float* __restrict__ g, const float* __restrict__ bvec,
             float* __restrict__ cls)
{
    int b = blockIdx.x;
    const float* xr = x + (long)b * TTOK * DMODEL;
    __shared__ float y[DMODEL];
    float s = 0.f, ss = 0.f;
    for (int i = threadIdx.x; i < DMODEL; i += 256) {
        float v = xr[i];
        y[i] = v;
        s  += v;
        ss += v * v;
    }
    float tsum  = blockReduceSum(s);
    float tsum2 = blockReduceSum(ss);
    float rstd1 = rsqrtf(tsum2 * (1.f / DMODEL) + 1e-6f);
    float mean  = rstd1 * tsum * (1.f / DMODEL);
    float ez2   = rstd1 * rstd1 * tsum2 * (1.f / DMODEL);
    float var   = ez2 - mean * mean;
    float rstd2 = rsqrtf(var + 1e-5f);
    __syncthreads();
    for (int i = threadIdx.x; i < DMODEL; i += 256) {
        float z = y[i] * rstd1;
        cls[(long)b * DMODEL + i] = (z - mean) * rstd2 * g[i] + bvec[i];
    }
}

__global__ __launch_bounds__(256)
void head_k(const float* __restrict__ cls, const float* __restrict__ w,
            const float* __restrict__ bias, float* __restrict__ out)
{
    int idx = blockIdx.x * blockDim.x + threadIdx.x;
    if (idx >= BATCH * NCLS) return;
    int b = idx / NCLS, c = idx - b * NCLS;
    const float* xr = cls + (long)b * DMODEL;
    float s = bias[c];
    #pragma unroll 4
    for (int k = 0; k < DMODEL; k++)
        s = fmaf(xr[k], w[(long)k * NCLS + c], s);
    out[idx] = s;
}

// ---------------------------------------------------------------------------
// Launch
// ---------------------------------------------------------------------------
extern "C" void kernel_launch(void* const* d_in, const int* in_sizes, int n_in,
                              void* d_out, int out_size)
{
    const float* img          = (const float*)d_in[0];
    const float* spt_ln_g     = (const float*)d_in[1];
    const float* spt_ln_b     = (const float*)d_in[2];
    const float* spt_w        = (const float*)d_in[3];
    const float* spt_b        = (const float*)d_in[4];
    const float* pos_emb      = (const float*)d_in[5];
    const float* cls_token    = (const float*)d_in[6];
    const float* lower_bounds = (const float*)d_in[7];
    const float* in_proj_w    = (const float*)d_in[8];
    const float* out_proj_w   = (const float*)d_in[9];
    const float* ff_w1        = (const float*)d_in[10];
    const float* ff_b1        = (const float*)d_in[11];
    const float* ff_w2        = (const float*)d_in[12];
    const float* ff_b2        = (const float*)d_in[13];
    const float* head_ln_g    = (const float*)d_in[14];
    const float* head_ln_b    = (const float*)d_in[15];
    const float* head_w       = (const float*)d_in[16];
    const float* head_b       = (const float*)d_in[17];

    __nv_bfloat16 *wh, *wl, *ph, *pl, *xnh, *xnl, *oh, *ol, *hmh, *hml;
    float *x, *feat, *lb, *cls;
    cudaGetSymbolAddress((void**)&wh,   g_wh);
    cudaGetSymbolAddress((void**)&wl,   g_wl);
    cudaGetSymbolAddress((void**)&ph,   g_ph);
    cudaGetSymbolAddress((void**)&pl,   g_pl);
    cudaGetSymbolAddress((void**)&xnh,  g_xnh);
    cudaGetSymbolAddress((void**)&xnl,  g_xnl);
    cudaGetSymbolAddress((void**)&oh,   g_oh);
    cudaGetSymbolAddress((void**)&ol,   g_ol);
    cudaGetSymbolAddress((void**)&hmh,  g_hmh);
    cudaGetSymbolAddress((void**)&hml,  g_hml);
    cudaGetSymbolAddress((void**)&x,    g_x);
    cudaGetSymbolAddress((void**)&feat, g_feat);
    cudaGetSymbolAddress((void**)&lb,   g_lb);
    cudaGetSymbolAddress((void**)&cls,  g_cls);

    static bool attr_done = false;
    if (!attr_done) {
        cudaFuncSetAttribute(mmagemm_k<EPI_STORE>,       cudaFuncAttributeMaxDynamicSharedMemorySize, SMTOT);
        cudaFuncSetAttribute(mmagemm_k<EPI_EMBED>,       cudaFuncAttributeMaxDynamicSharedMemorySize, SMTOT);
        cudaFuncSetAttribute(mmagemm_k<EPI_RESID>,       cudaFuncAttributeMaxDynamicSharedMemorySize, SMTOT);
        cudaFuncSetAttribute(mmagemm_k<EPI_GELU_PLANES>, cudaFuncAttributeMaxDynamicSharedMemorySize, SMTOT);
        cudaFuncSetAttribute(mmagemm_k<EPI_BIAS_RESID>,  cudaFuncAttributeMaxDynamicSharedMemorySize, SMTOT);
        attr_done = true;
    }

    // weight planes (once per launch; memory-bound, ~80us)
    cvtw_k<<<(WSZ_SPT/4 + 255)/256, 256>>>(spt_w,      wh + WOFF_SPT,  wl + WOFF_SPT,  WSZ_SPT);
    cvtw_k<<<(WSZ_INP/4 + 255)/256, 256>>>(in_proj_w,  wh + WOFF_INP,  wl + WOFF_INP,  WSZ_INP);
    cvtw_k<<<(WSZ_OUTP/4 + 255)/256, 256>>>(out_proj_w, wh + WOFF_OUTP, wl + WOFF_OUTP, WSZ_OUTP);
    cvtw_k<<<(WSZ_FF1/4 + 255)/256, 256>>>(ff_w1,      wh + WOFF_FF1,  wl + WOFF_FF1,  WSZ_FF1);
    cvtw_k<<<(WSZ_FF2/4 + 255)/256, 256>>>(ff_w2,      wh + WOFF_FF2,  wl + WOFF_FF2,  WSZ_FF2);

    patchln_k<<<NROWS_EMBED, 256>>>(img, spt_ln_g, spt_ln_b, ph, pl);
    lb_k<<<(DMODEL + 255) / 256, 256>>>(lower_bounds, lb);
    cls_k<<<(BATCH * DMODEL + 255) / 256, 256>>>(cls_token, pos_emb, x);

    {
        dim3 grid(DMODEL / 128, (NROWS_EMBED + 127) / 128);
        mmagemm_k<EPI_EMBED><<<grid, 256, SMTOT>>>(
            ph, pl, wh + WOFF_SPT, wl + WOFF_SPT,
            x, nullptr, spt_b, pos_emb, NROWS_EMBED, DMODEL, PD);
    }

    for (int i = 0; i < DEPTH; i++) {
        rmsnorm_k<<<NT, 256>>>(x, xnh, xnl);
        {
            dim3 grid((3 * DMODEL) / 128, (NT + 127) / 128);
            mmagemm_k<EPI_STORE><<<grid, 256, SMTOT>>>(
                xnh, xnl,
                wh + WOFF_INP + (size_t)i * DMODEL * 3 * DMODEL,
                wl + WOFF_INP + (size_t)i * DMODEL * 3 * DMODEL,
                feat, nullptr, nullptr, nullptr, NT, 3 * DMODEL, DMODEL);
        }
        hgru_k<<<(TTOK * NHEAD + 255) / 256, 256>>>(feat, lb + (size_t)i * DMODEL, oh, ol);
        {
            dim3 grid(DMODEL / 128, (NT + 127) / 128);
            mmagemm_k<EPI_RESID><<<grid, 256, SMTOT>>>(
                oh, ol,
                wh + WOFF_OUTP + (size_t)i * DMODEL * DMODEL,
                wl + WOFF_OUTP + (size_t)i * DMODEL * DMODEL,
                x, nullptr, nullptr, nullptr, NT, DMODEL, DMODEL);
        }
        rmsnorm_k<<<NT, 256>>>(x, xnh, xnl);
        {
            dim3 grid(MLP / 128, (NT + 127) / 128);
            mmagemm_k<EPI_GELU_PLANES><<<grid, 256, SMTOT>>>(
                xnh, xnl,
                wh + WOFF_FF1 + (size_t)i * DMODEL * MLP,
                wl + WOFF_FF1 + (size_t)i * DMODEL * MLP,
                hmh, hml, ff_b1 + (size_t)i * MLP, nullptr, NT, MLP, DMODEL);
        }
        {
            dim3 grid(DMODEL / 128, (NT + 127) / 128);
            mmagemm_k<EPI_BIAS_RESID><<<grid, 256, SMTOT>>>(
                hmh, hml,
                wh + WOFF_FF2 + (size_t)i * MLP * DMODEL,
                wl + WOFF_FF2 + (size_t)i * MLP * DMODEL,
                x, nullptr, ff_b2 + (size_t)i * DMODEL, nullptr, NT, DMODEL, MLP);
        }
    }

    final_k<<<BATCH, 256>>>(x, head_ln_g, head_ln_b, cls);
    head_k<<<(BATCH * NCLS + 255) / 256, 256>>>(cls, head_w, head_b, (float*)d_out);
}

// round 5
// speedup vs baseline: 2.6207x; 1.0919x over previous
#include <cuda_runtime.h>
#include <cuda_bf16.h>
#include <math.h>
#include <stdint.h>

// ---------------------------------------------------------------------------
// Problem constants
// ---------------------------------------------------------------------------
#define BATCH   16
#define CIN     3
#define IMG     256
#define PSZ     16
#define NPATCH  256
#define C5      15
#define PD      3840
#define DMODEL  768
#define DEPTH   8
#define MLP     3072
#define NCLS    1000
#define TTOK    257
#define NT      (BATCH*TTOK)        // 4112
#define NROWS_EMBED (BATCH*NPATCH)  // 4096
#define NHEAD   384

// weight plane offsets (elements)
#define WOFF_SPT  0
#define WSZ_SPT   (PD*DMODEL)
#define WOFF_INP  (WOFF_SPT + WSZ_SPT)
#define WSZ_INP   (DEPTH*DMODEL*3*DMODEL)
#define WOFF_OUTP (WOFF_INP + WSZ_INP)
#define WSZ_OUTP  (DEPTH*DMODEL*DMODEL)
#define WOFF_FF1  (WOFF_OUTP + WSZ_OUTP)
#define WSZ_FF1   (DEPTH*DMODEL*MLP)
#define WOFF_FF2  (WOFF_FF1 + WSZ_FF1)
#define WSZ_FF2   (DEPTH*MLP*DMODEL)
#define WTOT      (WOFF_FF2 + WSZ_FF2)

// ---------------------------------------------------------------------------
// Scratch (device globals)
// ---------------------------------------------------------------------------
__device__ __nv_bfloat16 g_wh[WTOT];
__device__ __nv_bfloat16 g_wl[WTOT];
__device__ __nv_bfloat16 g_ph[NROWS_EMBED * PD];
__device__ __nv_bfloat16 g_pl[NROWS_EMBED * PD];
__device__ __nv_bfloat16 g_xnh[NT * DMODEL];
__device__ __nv_bfloat16 g_xnl[NT * DMODEL];
__device__ __nv_bfloat16 g_oh[NT * DMODEL];
__device__ __nv_bfloat16 g_ol[NT * DMODEL];
__device__ __nv_bfloat16 g_hmh[NT * MLP];
__device__ __nv_bfloat16 g_hml[NT * MLP];
__device__ float g_x[NT * DMODEL];
__device__ float g_feat[NT * 3 * DMODEL];
__device__ float g_lb[DEPTH * DMODEL];
__device__ float g_cls[BATCH * DMODEL];

// ---------------------------------------------------------------------------
// Helpers
// ---------------------------------------------------------------------------
__device__ __forceinline__ uint32_t smem_u32(const void* p) {
    uint32_t a;
    asm("{ .reg .u64 t; cvta.to.shared.u64 t, %1; cvt.u32.u64 %0, t; }"
        : "=r"(a) : "l"(p));
    return a;
}
__device__ __forceinline__ void ldsm4(uint32_t* r, uint32_t addr) {
    asm volatile("ldmatrix.sync.aligned.m8n8.x4.shared.b16 {%0,%1,%2,%3}, [%4];"
                 : "=r"(r[0]), "=r"(r[1]), "=r"(r[2]), "=r"(r[3]) : "r"(addr));
}
__device__ __forceinline__ void ldsm4t(uint32_t* r, uint32_t addr) {
    asm volatile("ldmatrix.sync.aligned.m8n8.x4.trans.shared.b16 {%0,%1,%2,%3}, [%4];"
                 : "=r"(r[0]), "=r"(r[1]), "=r"(r[2]), "=r"(r[3]) : "r"(addr));
}
__device__ __forceinline__ void mma16816(float* d, const uint32_t* a, const uint32_t* b) {
    asm volatile(
        "mma.sync.aligned.m16n8k16.row.col.f32.bf16.bf16.f32 "
        "{%0,%1,%2,%3}, {%4,%5,%6,%7}, {%8,%9}, {%0,%1,%2,%3};"
        : "+f"(d[0]), "+f"(d[1]), "+f"(d[2]), "+f"(d[3])
        : "r"(a[0]), "r"(a[1]), "r"(a[2]), "r"(a[3]), "r"(b[0]), "r"(b[1]));
}
__device__ __forceinline__ void cpasync16(uint32_t dst, const void* src, uint32_t n) {
    asm volatile("cp.async.cg.shared.global [%0], [%1], 16, %2;"
                 :: "r"(dst), "l"(src), "r"(n) : "memory");
}
__device__ __forceinline__ void cp_commit() {
    asm volatile("cp.async.commit_group;" ::: "memory");
}
template<int N>
__device__ __forceinline__ void cp_wait() {
    asm volatile("cp.async.wait_group %0;" :: "n"(N) : "memory");
}

__device__ __forceinline__ float gelu_exact(float x) {
    return 0.5f * x * (1.f + erff(x * 0.70710678118654752440f));
}

__device__ __forceinline__ float blockReduceSum(float v) {
    __shared__ float sh[32];
    __shared__ float res;
    int lane = threadIdx.x & 31;
    int wid  = threadIdx.x >> 5;
    #pragma unroll
    for (int o = 16; o > 0; o >>= 1) v += __shfl_down_sync(0xffffffffu, v, o);
    if (lane == 0) sh[wid] = v;
    __syncthreads();
    int nw = (blockDim.x + 31) >> 5;
    v = (threadIdx.x < nw) ? sh[threadIdx.x] : 0.f;
    if (wid == 0) {
        #pragma unroll
        for (int o = 16; o > 0; o >>= 1) v += __shfl_down_sync(0xffffffffu, v, o);
        if (lane == 0) res = v;
    }
    __syncthreads();
    return res;
}

// fp32 -> (hi, lo) bf16
__device__ __forceinline__ void f2bf2(float v, uint32_t& h, uint32_t& l) {
    __nv_bfloat16 bh = __float2bfloat16_rn(v);
    float r = v - __bfloat162float(bh);
    __nv_bfloat16 bl = __float2bfloat16_rn(r);
    h = (uint32_t)__bfloat16_as_ushort(bh);
    l = (uint32_t)__bfloat16_as_ushort(bl);
}
__device__ __forceinline__ void cvt4(float4 v, uint2& h, uint2& l) {
    uint32_t h0,l0,h1,l1,h2,l2,h3,l3;
    f2bf2(v.x, h0, l0); f2bf2(v.y, h1, l1);
    f2bf2(v.z, h2, l2); f2bf2(v.w, h3, l3);
    h = make_uint2(h0 | (h1 << 16), h2 | (h3 << 16));
    l = make_uint2(l0 | (l1 << 16), l2 | (l3 << 16));
}

// ---------------------------------------------------------------------------
// Weight pre-conversion
// ---------------------------------------------------------------------------
__global__ __launch_bounds__(256)
void cvtw_k(const float* __restrict__ x, __nv_bfloat16* __restrict__ h,
            __nv_bfloat16* __restrict__ l, int n)
{
    int i = (blockIdx.x * blockDim.x + threadIdx.x) * 4;
    if (i >= n) return;
    float4 v = *reinterpret_cast<const float4*>(x + i);
    uint2 hh, ll;
    cvt4(v, hh, ll);
    *reinterpret_cast<uint2*>(h + i) = hh;
    *reinterpret_cast<uint2*>(l + i) = ll;
}

// ---------------------------------------------------------------------------
// HMMA GEMM, bf16 hi/lo 3-pass, cp.async 3-stage pipeline.
// CTA tile 128x128, K-chunk 32, 16 warps (4m x 4n), warp tile 32x32.
// ---------------------------------------------------------------------------
#define EPI_STORE       0
#define EPI_EMBED       1
#define EPI_RESID       2
#define EPI_GELU_PLANES 3
#define EPI_BIAS_RESID  4

#define NTHREADS 512
#define APITCH 80
#define BPITCH 272
#define OFF_AH 0
#define OFF_AL 10240
#define OFF_BH 20480
#define OFF_BL 29184
#define SBUF   37888
#define STAGES 3
#define SMTOT  (STAGES*SBUF)   // 113664

__device__ __forceinline__ void stage_load(uint32_t sb,
                                           const __nv_bfloat16* __restrict__ Ah,
                                           const __nv_bfloat16* __restrict__ Al,
                                           const __nv_bfloat16* __restrict__ Bh,
                                           const __nv_bfloat16* __restrict__ Bl,
                                           int M, int N, int K,
                                           int rowBase, int colBase, int s, int tid)
{
    const int k0 = s << 5;
    {
        int row = tid >> 2;
        int seg = tid & 3;
        int gr  = rowBase + row;
        uint32_t nbytes = (gr < M) ? 16u : 0u;
        int grs = (gr < M) ? gr : (M - 1);
        size_t goff = (size_t)grs * K + k0 + seg * 8;
        uint32_t so = (uint32_t)(row * APITCH + seg * 16);
        cpasync16(sb + OFF_AH + so, Ah + goff, nbytes);
        cpasync16(sb + OFF_AL + so, Al + goff, nbytes);
    }
    {
        int row = tid >> 4;
        int seg = tid & 15;
        size_t goff = (size_t)(k0 + row) * N + colBase + seg * 8;
        uint32_t so = (uint32_t)(row * BPITCH + seg * 16);
        cpasync16(sb + OFF_BH + so, Bh + goff, 16u);
        cpasync16(sb + OFF_BL + so, Bl + goff, 16u);
    }
}

__device__ __forceinline__ void compute_chunk(uint32_t sbuf, int lane, int wm, int wn,
                                              float acc[2][4][4])
{
    #pragma unroll
    for (int k16 = 0; k16 < 32; k16 += 16) {
        uint32_t aH[2][4], aL[2][4], bH[2][4], bL[2][4];
        const uint32_t arow = (uint32_t)(wm + (lane & 7) + (lane & 8));
        const uint32_t aoff = arow * APITCH + (uint32_t)(k16 + ((lane & 16) >> 1)) * 2;
        #pragma unroll
        for (int mb = 0; mb < 2; mb++) {
            ldsm4(aH[mb], sbuf + OFF_AH + aoff + mb * 16 * APITCH);
            ldsm4(aL[mb], sbuf + OFF_AL + aoff + mb * 16 * APITCH);
        }
        const uint32_t brow = (uint32_t)(k16 + (lane & 7) + ((lane & 16) >> 1));
        const uint32_t boff = brow * BPITCH + (uint32_t)(wn + (lane & 8)) * 2;
        #pragma unroll
        for (int nb2 = 0; nb2 < 2; nb2++) {
            ldsm4t(bH[nb2], sbuf + OFF_BH + boff + nb2 * 32);
            ldsm4t(bL[nb2], sbuf + OFF_BL + boff + nb2 * 32);
        }
        #pragma unroll
        for (int mb = 0; mb < 2; mb++) {
            #pragma unroll
            for (int nb = 0; nb < 4; nb++) {
                uint32_t bh[2] = { bH[nb >> 1][nb & 1], bH[nb >> 1][(nb & 1) + 2] };
                uint32_t bl[2] = { bL[nb >> 1][nb & 1], bL[nb >> 1][(nb & 1) + 2] };
                mma16816(acc[mb][nb], aH[mb], bh);
                mma16816(acc[mb][nb], aH[mb], bl);
                mma16816(acc[mb][nb], aL[mb], bh);
            }
        }
    }
}

template<int EPI>
__global__ __launch_bounds__(NTHREADS, 1)
void mmagemm_k(const __nv_bfloat16* __restrict__ Ah, const __nv_bfloat16* __restrict__ Al,
               const __nv_bfloat16* __restrict__ Bh, const __nv_bfloat16* __restrict__ Bl,
               void* __restrict__ Cv, void* __restrict__ C2v,
               const float* __restrict__ bias, const float* __restrict__ extra,
               int M, int N, int K)
{
    extern __shared__ char smem[];
    const uint32_t sbase = smem_u32(smem);
    const int tid  = threadIdx.x;
    const int lane = tid & 31;
    const int wid  = tid >> 5;
    const int wm   = (wid >> 2) * 32;   // 4 m-warps
    const int wn   = (wid & 3) * 32;    // 4 n-warps
    const int rowBase = blockIdx.y * 128;
    const int colBase = blockIdx.x * 128;
    const int nc = K >> 5;

    float acc[2][4][4];
    #pragma unroll
    for (int a = 0; a < 2; a++)
        #pragma unroll
        for (int b = 0; b < 4; b++)
            #pragma unroll
            for (int c = 0; c < 4; c++) acc[a][b][c] = 0.f;

    #pragma unroll
    for (int s = 0; s < STAGES - 1; s++) {
        if (s < nc)
            stage_load(sbase + s * SBUF, Ah, Al, Bh, Bl, M, N, K, rowBase, colBase, s, tid);
        cp_commit();
    }

    for (int c = 0; c < nc; c++) {
        cp_wait<STAGES - 2>();
        __syncthreads();
        int s = c + STAGES - 1;
        if (s < nc)
            stage_load(sbase + (s % STAGES) * SBUF, Ah, Al, Bh, Bl, M, N, K,
                       rowBase, colBase, s, tid);
        cp_commit();
        compute_chunk(sbase + (c % STAGES) * SBUF, lane, wm, wn, acc);
    }

    // ---- epilogue ----
    const int mrow = rowBase + wm + (lane >> 2);
    const int mcol = colBase + wn + (lane & 3) * 2;
    #pragma unroll
    for (int mi = 0; mi < 2; mi++) {
        #pragma unroll
        for (int hf = 0; hf < 2; hf++) {
            const int row = mrow + mi * 16 + hf * 8;
            if (row >= M) continue;
            #pragma unroll
            for (int ni = 0; ni < 4; ni++) {
                const int col = mcol + ni * 8;
                float v0 = acc[mi][ni][hf * 2];
                float v1 = acc[mi][ni][hf * 2 + 1];
                if (EPI == EPI_STORE) {
                    float* C = (float*)Cv;
                    *reinterpret_cast<float2*>(C + (size_t)row * N + col) =
                        make_float2(v0, v1);
                } else if (EPI == EPI_EMBED) {
                    float* C = (float*)Cv;
                    int b  = row >> 8;
                    int tl = row & 255;
                    float2 bb = *reinterpret_cast<const float2*>(bias + col);
                    float2 pp = *reinterpret_cast<const float2*>(extra + (size_t)(tl + 1) * N + col);
                    *reinterpret_cast<float2*>(C + ((size_t)b * TTOK + 1 + tl) * N + col) =
                        make_float2(v0 + bb.x + pp.x, v1 + bb.y + pp.y);
                } else if (EPI == EPI_RESID) {
                    float* C = (float*)Cv;
                    float2* o = reinterpret_cast<float2*>(C + (size_t)row * N + col);
                    float2 cc = *o;
                    *o = make_float2(cc.x + v0, cc.y + v1);
                } else if (EPI == EPI_GELU_PLANES) {
                    __nv_bfloat16* Hh = (__nv_bfloat16*)Cv;
                    __nv_bfloat16* Hl = (__nv_bfloat16*)C2v;
                    float2 bb = *reinterpret_cast<const float2*>(bias + col);
                    float g0 = gelu_exact(v0 + bb.x);
                    float g1 = gelu_exact(v1 + bb.y);
                    uint32_t h0,l0,h1,l1;
                    f2bf2(g0, h0, l0); f2bf2(g1, h1, l1);
                    size_t off = (size_t)row * N + col;
                    *reinterpret_cast<uint32_t*>(Hh + off) = h0 | (h1 << 16);
                    *reinterpret_cast<uint32_t*>(Hl + off) = l0 | (l1 << 16);
                } else if (EPI == EPI_BIAS_RESID) {
                    float* C = (float*)Cv;
                    float2 bb = *reinterpret_cast<const float2*>(bias + col);
                    float2* o = reinterpret_cast<float2*>(C + (size_t)row * N + col);
                    float2 cc = *o;
                    *o = make_float2(cc.x + v0 + bb.x, cc.y + v1 + bb.y);
                }
            }
        }
    }
}

// ---------------------------------------------------------------------------
// Shifted-patch extraction + LayerNorm -> bf16 hi/lo planes
// ---------------------------------------------------------------------------
__global__ __launch_bounds__(256)
void patchln_k(const float* __restrict__ img,
               const float* __restrict__ ln_g,
               const float* __restrict__ ln_b,
               __nv_bfloat16* __restrict__ ph,
               __nv_bfloat16* __restrict__ pl)
{
    const int blk = blockIdx.x;
    const int b   = blk >> 8;
    const int pt  = blk & 255;
    const int phh = pt >> 4;
    const int pw  = pt & 15;

    __shared__ float vals[PD];

    const int sh_tab[5] = {0, 0, 0, 1, -1};
    const int sw_tab[5] = {0, 1, -1, 0, 0};

    float s = 0.f, ss = 0.f;
    for (int f = threadIdx.x; f < PD; f += 256) {
        int py  = f / (PSZ * C5);
        int rem = f - py * (PSZ * C5);
        int px  = rem / C5;
        int c   = rem - px * C5;
        int g   = c / CIN;
        int ch  = c - g * CIN;
        int row = phh * PSZ + py - sh_tab[g];
        int col = pw * PSZ + px - sw_tab[g];
        float v = 0.f;
        if (row >= 0 && row < IMG && col >= 0 && col < IMG)
            v = img[(((long)b * CIN + ch) * IMG + row) * IMG + col];
        vals[f] = v;
        s  += v;
        ss += v * v;
    }
    float tsum  = blockReduceSum(s);
    float tsum2 = blockReduceSum(ss);
    float mean  = tsum * (1.f / PD);
    float var   = tsum2 * (1.f / PD) - mean * mean;
    float rstd  = rsqrtf(var + 1e-5f);
    __syncthreads();
    size_t rowoff = (size_t)blk * PD;
    for (int f = threadIdx.x; f < PD; f += 256) {
        float y = (vals[f] - mean) * rstd * ln_g[f] + ln_b[f];
        uint32_t hh, ll;
        f2bf2(y, hh, ll);
        ph[rowoff + f] = __ushort_as_bfloat16((unsigned short)hh);
        pl[rowoff + f] = __ushort_as_bfloat16((unsigned short)ll);
    }
}

// ---------------------------------------------------------------------------
__global__ void lb_k(const float* __restrict__ lbin, float* __restrict__ lbout)
{
    int d = blockIdx.x * blockDim.x + threadIdx.x;
    if (d >= DMODEL) return;
    float v[DEPTH];
    float m = -1e30f;
    #pragma unroll
    for (int i = 0; i < DEPTH; i++) { v[i] = lbin[i * DMODEL + d]; m = fmaxf(m, v[i]); }
    float s = 0.f;
    #pragma unroll
    for (int i = 0; i < DEPTH; i++) { v[i] = expf(v[i] - m); s += v[i]; }
    float inv = 1.f / s;
    float c = 0.f;
    float c0 = v[0] * inv;
    #pragma unroll
    for (int i = 0; i < DEPTH; i++) { c += v[i] * inv; lbout[i * DMODEL + d] = c - c0; }
}

__global__ void cls_k(const float* __restrict__ cls_token,
                      const float* __restrict__ pos,
                      float* __restrict__ x)
{
    int i = blockIdx.x * blockDim.x + threadIdx.x;
    if (i >= BATCH * DMODEL) return;
    int b = i / DMODEL, d = i - b * DMODEL;
    x[(long)b * TTOK * DMODEL + d] = cls_token[d] + pos[d];
}

// RMSNorm -> bf16 hi/lo planes
__global__ __launch_bounds__(256)
void rmsnorm_k(const float* __restrict__ x,
               __nv_bfloat16* __restrict__ yh, __nv_bfloat16* __restrict__ yl)
{
    const long row = blockIdx.x;
    const float* xr = x + row * DMODEL;
    float s = 0.f;
    for (int i = threadIdx.x; i < DMODEL; i += 256) { float v = xr[i]; s += v * v; }
    float tot = blockReduceSum(s);
    float r = rsqrtf(tot * (1.f / DMODEL) + 1e-6f);
    size_t off = (size_t)row * DMODEL;
    for (int i = threadIdx.x; i < DMODEL; i += 256) {
        uint32_t hh, ll;
        f2bf2(xr[i] * r, hh, ll);
        yh[off + i] = __ushort_as_bfloat16((unsigned short)hh);
        yl[off + i] = __ushort_as_bfloat16((unsigned short)ll);
    }
}

// hGRU2 scan -> bf16 hi/lo planes
__global__ __launch_bounds__(256)
void hgru_k(const float* __restrict__ feat, const float* __restrict__ lb,
            __nv_bfloat16* __restrict__ oh, __nv_bfloat16* __restrict__ ol)
{
    int e = blockIdx.x * blockDim.x + threadIdx.x;
    if (e >= TTOK * NHEAD) return;
    int t = e / NHEAD;
    int h = e - t * NHEAD;

    float lb0 = lb[2 * h];
    float lb1 = lb[2 * h + 1];
    float S00 = 0.f, S01 = 0.f, S10 = 0.f, S11 = 0.f;

    #pragma unroll 1
    for (int n = 0; n < BATCH; n++) {
        const float* r = feat + (long)(n * TTOK + t) * (3 * DMODEL);
        float2 vv = *(const float2*)(r + 2 * h);
        float2 qq = *(const float2*)(r + DMODEL + 2 * h);
        float2 ff = *(const float2*)(r + 2 * DMODEL + 2 * h);
        float v0 = gelu_exact(vv.x), v1 = gelu_exact(vv.y);
        float q0 = gelu_exact(qq.x), q1 = gelu_exact(qq.y);
        float s0 = 1.f / (1.f + expf(-ff.x));
        float s1 = 1.f / (1.f + expf(-ff.y));
        float lam0 = lb0 + (1.f - lb0) * s0;
        float lam1 = lb1 + (1.f - lb1) * s1;
        float k0 = 1.f - lam0, k1 = 1.f - lam1;
        S00 = lam0 * S00 + k0 * v0;  S01 = lam0 * S01 + k0 * v1;
        S10 = lam1 * S10 + k1 * v0;  S11 = lam1 * S11 + k1 * v1;
        float o0 = q0 * S00 + q1 * S10;
        float o1 = q0 * S01 + q1 * S11;
        uint32_t h0,l0,h1,l1;
        f2bf2(o0, h0, l0); f2bf2(o1, h1, l1);
        size_t off = (size_t)(n * TTOK + t) * DMODEL + 2 * h;
        *reinterpret_cast<uint32_t*>(oh + off) = h0 | (h1 << 16);
        *reinterpret_cast<uint32_t*>(ol + off) = l0 | (l1 << 16);
    }
}

__global__ __launch_bounds__(256)
void final_k(const float* __restrict__ x,
             const float* __restrict__ g, const float* __restrict__ bvec,
             float* __restrict__ cls)
{
    int b = blockIdx.x;
    const float* xr = x + (long)b * TTOK * DMODEL;
    __shared__ float y[DMODEL];
    float s = 0.f, ss = 0.f;
    for (int i = threadIdx.x; i < DMODEL; i += 256) {
        float v = xr[i];
        y[i] = v;
        s  += v;
        ss += v * v;
    }
    float tsum  = blockReduceSum(s);
    float tsum2 = blockReduceSum(ss);
    float rstd1 = rsqrtf(tsum2 * (1.f / DMODEL) + 1e-6f);
    float mean  = rstd1 * tsum * (1.f / DMODEL);
    float ez2   = rstd1 * rstd1 * tsum2 * (1.f / DMODEL);
    float var   = ez2 - mean * mean;
    float rstd2 = rsqrtf(var + 1e-5f);
    __syncthreads();
    for (int i = threadIdx.x; i < DMODEL; i += 256) {
        float z = y[i] * rstd1;
        cls[(long)b * DMODEL + i] = (z - mean) * rstd2 * g[i] + bvec[i];
    }
}

__global__ __launch_bounds__(256)
void head_k(const float* __restrict__ cls, const float* __restrict__ w,
            const float* __restrict__ bias, float* __restrict__ out)
{
    int idx = blockIdx.x * blockDim.x + threadIdx.x;
    if (idx >= BATCH * NCLS) return;
    int b = idx / NCLS, c = idx - b * NCLS;
    const float* xr = cls + (long)b * DMODEL;
    float s = bias[c];
    #pragma unroll 4
    for (int k = 0; k < DMODEL; k++)
        s = fmaf(xr[k], w[(long)k * NCLS + c], s);
    out[idx] = s;
}

// ---------------------------------------------------------------------------
// Launch
// ---------------------------------------------------------------------------
extern "C" void kernel_launch(void* const* d_in, const int* in_sizes, int n_in,
                              void* d_out, int out_size)
{
    const float* img          = (const float*)d_in[0];
    const float* spt_ln_g     = (const float*)d_in[1];
    const float* spt_ln_b     = (const float*)d_in[2];
    const float* spt_w        = (const float*)d_in[3];
    const float* spt_b        = (const float*)d_in[4];
    const float* pos_emb      = (const float*)d_in[5];
    const float* cls_token    = (const float*)d_in[6];
    const float* lower_bounds = (const float*)d_in[7];
    const float* in_proj_w    = (const float*)d_in[8];
    const float* out_proj_w   = (const float*)d_in[9];
    const float* ff_w1        = (const float*)d_in[10];
    const float* ff_b1        = (const float*)d_in[11];
    const float* ff_w2        = (const float*)d_in[12];
    const float* ff_b2        = (const float*)d_in[13];
    const float* head_ln_g    = (const float*)d_in[14];
    const float* head_ln_b    = (const float*)d_in[15];
    const float* head_w       = (const float*)d_in[16];
    const float* head_b       = (const float*)d_in[17];

    __nv_bfloat16 *wh, *wl, *ph, *pl, *xnh, *xnl, *oh, *ol, *hmh, *hml;
    float *x, *feat, *lb, *cls;
    cudaGetSymbolAddress((void**)&wh,   g_wh);
    cudaGetSymbolAddress((void**)&wl,   g_wl);
    cudaGetSymbolAddress((void**)&ph,   g_ph);
    cudaGetSymbolAddress((void**)&pl,   g_pl);
    cudaGetSymbolAddress((void**)&xnh,  g_xnh);
    cudaGetSymbolAddress((void**)&xnl,  g_xnl);
    cudaGetSymbolAddress((void**)&oh,   g_oh);
    cudaGetSymbolAddress((void**)&ol,   g_ol);
    cudaGetSymbolAddress((void**)&hmh,  g_hmh);
    cudaGetSymbolAddress((void**)&hml,  g_hml);
    cudaGetSymbolAddress((void**)&x,    g_x);
    cudaGetSymbolAddress((void**)&feat, g_feat);
    cudaGetSymbolAddress((void**)&lb,   g_lb);
    cudaGetSymbolAddress((void**)&cls,  g_cls);

    static bool attr_done = false;
    if (!attr_done) {
        cudaFuncSetAttribute(mmagemm_k<EPI_STORE>,       cudaFuncAttributeMaxDynamicSharedMemorySize, SMTOT);
        cudaFuncSetAttribute(mmagemm_k<EPI_EMBED>,       cudaFuncAttributeMaxDynamicSharedMemorySize, SMTOT);
        cudaFuncSetAttribute(mmagemm_k<EPI_RESID>,       cudaFuncAttributeMaxDynamicSharedMemorySize, SMTOT);
        cudaFuncSetAttribute(mmagemm_k<EPI_GELU_PLANES>, cudaFuncAttributeMaxDynamicSharedMemorySize, SMTOT);
        cudaFuncSetAttribute(mmagemm_k<EPI_BIAS_RESID>,  cudaFuncAttributeMaxDynamicSharedMemorySize, SMTOT);
        attr_done = true;
    }

    cvtw_k<<<(WSZ_SPT/4 + 255)/256, 256>>>(spt_w,      wh + WOFF_SPT,  wl + WOFF_SPT,  WSZ_SPT);
    cvtw_k<<<(WSZ_INP/4 + 255)/256, 256>>>(in_proj_w,  wh + WOFF_INP,  wl + WOFF_INP,  WSZ_INP);
    cvtw_k<<<(WSZ_OUTP/4 + 255)/256, 256>>>(out_proj_w, wh + WOFF_OUTP, wl + WOFF_OUTP, WSZ_OUTP);
    cvtw_k<<<(WSZ_FF1/4 + 255)/256, 256>>>(ff_w1,      wh + WOFF_FF1,  wl + WOFF_FF1,  WSZ_FF1);
    cvtw_k<<<(WSZ_FF2/4 + 255)/256, 256>>>(ff_w2,      wh + WOFF_FF2,  wl + WOFF_FF2,  WSZ_FF2);

    patchln_k<<<NROWS_EMBED, 256>>>(img, spt_ln_g, spt_ln_b, ph, pl);
    lb_k<<<(DMODEL + 255) / 256, 256>>>(lower_bounds, lb);
    cls_k<<<(BATCH * DMODEL + 255) / 256, 256>>>(cls_token, pos_emb, x);

    {
        dim3 grid(DMODEL / 128, (NROWS_EMBED + 127) / 128);
        mmagemm_k<EPI_EMBED><<<grid, NTHREADS, SMTOT>>>(
            ph, pl, wh + WOFF_SPT, wl + WOFF_SPT,
            x, nullptr, spt_b, pos_emb, NROWS_EMBED, DMODEL, PD);
    }

    for (int i = 0; i < DEPTH; i++) {
        rmsnorm_k<<<NT, 256>>>(x, xnh, xnl);
        {
            dim3 grid((3 * DMODEL) / 128, (NT + 127) / 128);
            mmagemm_k<EPI_STORE><<<grid, NTHREADS, SMTOT>>>(
                xnh, xnl,
                wh + WOFF_INP + (size_t)i * DMODEL * 3 * DMODEL,
                wl + WOFF_INP + (size_t)i * DMODEL * 3 * DMODEL,
                feat, nullptr, nullptr, nullptr, NT, 3 * DMODEL, DMODEL);
        }
        hgru_k<<<(TTOK * NHEAD + 255) / 256, 256>>>(feat, lb + (size_t)i * DMODEL, oh, ol);
        {
            dim3 grid(DMODEL / 128, (NT + 127) / 128);
            mmagemm_k<EPI_RESID><<<grid, NTHREADS, SMTOT>>>(
                oh, ol,
                wh + WOFF_OUTP + (size_t)i * DMODEL * DMODEL,
                wl + WOFF_OUTP + (size_t)i * DMODEL * DMODEL,
                x, nullptr, nullptr, nullptr, NT, DMODEL, DMODEL);
        }
        rmsnorm_k<<<NT, 256>>>(x, xnh, xnl);
        {
            dim3 grid(MLP / 128, (NT + 127) / 128);
            mmagemm_k<EPI_GELU_PLANES><<<grid, NTHREADS, SMTOT>>>(
                xnh, xnl,
                wh + WOFF_FF1 + (size_t)i * DMODEL * MLP,
                wl + WOFF_FF1 + (size_t)i * DMODEL * MLP,
                hmh, hml, ff_b1 + (size_t)i * MLP, nullptr, NT, MLP, DMODEL);
        }
        {
            dim3 grid(DMODEL / 128, (NT + 127) / 128);
            mmagemm_k<EPI_BIAS_RESID><<<grid, NTHREADS, SMTOT>>>(
                hmh, hml,
                wh + WOFF_FF2 + (size_t)i * MLP * DMODEL,
                wl + WOFF_FF2 + (size_t)i * MLP * DMODEL,
                x, nullptr, ff_b2 + (size_t)i * DMODEL, nullptr, NT, DMODEL, MLP);
        }
    }

    final_k<<<BATCH, 256>>>(x, head_ln_g, head_ln_b, cls);
    head_k<<<(BATCH * NCLS + 255) / 256, 256>>>(cls, head_w, head_b, (float*)d_out);
}